// round 2
// baseline (speedup 1.0000x reference)
#include <cuda_runtime.h>
#include <cstdint>

#define BB   2
#define CC   256
#define NN   2304
#define OC3  768
#define NH   8
#define HD   32

// Scratch (device globals — allocation-free)
__device__ float g_Y [BB * NN * OC3];   // qkv output [b][n][768]
__device__ float g_Kt[BB * CC * NN];    // K transposed [b][h*32+d][n]
__device__ float g_O [BB * NN * CC];    // attention out [b][n][c]

// ---------- packed f32x2 helpers ----------
__device__ __forceinline__ unsigned long long pack2(float x, float y) {
    unsigned long long r;
    asm("mov.b64 %0, {%1, %2};" : "=l"(r) : "f"(x), "f"(y));
    return r;
}
__device__ __forceinline__ void unpack2(unsigned long long v, float& x, float& y) {
    asm("mov.b64 {%0, %1}, %2;" : "=f"(x), "=f"(y) : "l"(v));
}
__device__ __forceinline__ void fma2(unsigned long long& d, unsigned long long a, unsigned long long b) {
    asm("fma.rn.f32x2 %0, %1, %2, %3;" : "=l"(d) : "l"(a), "l"(b), "l"(d));
}
__device__ __forceinline__ unsigned long long mul2(unsigned long long a, unsigned long long b) {
    unsigned long long r;
    asm("mul.rn.f32x2 %0, %1, %2;" : "=l"(r) : "l"(a), "l"(b));
    return r;
}

// ---------- cp.async helpers ----------
#define CP_ASYNC16(dst, src) \
    asm volatile("cp.async.cg.shared.global [%0], [%1], 16;" :: "r"(dst), "l"(src))
#define CP_COMMIT() asm volatile("cp.async.commit_group;")
#define CP_WAIT0()  asm volatile("cp.async.wait_group 0;" ::: "memory")

__device__ __forceinline__ uint32_t sptr(const void* p) {
    return (uint32_t)__cvta_generic_to_shared(p);
}

// =====================================================================
// Kernel 1: QKV GEMM. Y[b][n][o] = sum_c W[o][c] X[b][c][n] + bias[o]
// Tile 128o x 128n, Kc=8, 256 threads, 8x8 microtile, double-buffered.
// K slice (o in [256,512)) additionally written transposed to g_Kt.
// =====================================================================
__global__ __launch_bounds__(256, 2) void qkv_kernel(
    const float* __restrict__ X, const float* __restrict__ W,
    const float* __restrict__ bias)
{
    __shared__ float As[2][8][128];  // [c][o]
    __shared__ float Bs[2][8][128];  // [c][n]

    const int b  = blockIdx.z;
    const int n0 = blockIdx.x * 128;
    const int o0 = blockIdx.y * 128;
    const int t  = threadIdx.x;
    const int tx = t & 15, ty = t >> 4;

    const float* Xb = X + (size_t)b * CC * NN;

    // loaders
    const int wo  = t & 127, wc4 = (t >> 7) << 2;   // W: o row, c col4
    const int xc  = t >> 5,  xn4 = (t & 31) << 2;   // X: c row, n col4
    const uint32_t bsBase = sptr(&Bs[0][0][0]);

    unsigned long long acc[8][4];
    #pragma unroll
    for (int i = 0; i < 8; i++)
        #pragma unroll
        for (int j = 0; j < 4; j++) acc[i][j] = 0ULL;

    // preload stage 0
    float4 wreg = *(const float4*)(W + (size_t)(o0 + wo) * CC + wc4);
    CP_ASYNC16(bsBase + (xc * 128 + xn4) * 4, Xb + (size_t)xc * NN + n0 + xn4);
    CP_COMMIT();
    CP_WAIT0();
    As[0][wc4 + 0][wo] = wreg.x; As[0][wc4 + 1][wo] = wreg.y;
    As[0][wc4 + 2][wo] = wreg.z; As[0][wc4 + 3][wo] = wreg.w;
    __syncthreads();

    #pragma unroll 1
    for (int it = 0; it < 32; it++) {
        const int cur = it & 1;
        if (it < 31) {
            const int c0 = (it + 1) * 8;
            CP_ASYNC16(bsBase + ((1 - cur) * 1024 + xc * 128 + xn4) * 4,
                       Xb + (size_t)(c0 + xc) * NN + n0 + xn4);
            CP_COMMIT();
            wreg = *(const float4*)(W + (size_t)(o0 + wo) * CC + c0 + wc4);
        }

        #pragma unroll
        for (int kk = 0; kk < 8; kk++) {
            float a[8];
            *(float4*)&a[0] = *(const float4*)&Bs[cur][kk][ty * 8];
            *(float4*)&a[4] = *(const float4*)&Bs[cur][kk][ty * 8 + 4];
            ulonglong2 b0 = *(const ulonglong2*)&As[cur][kk][tx * 8];
            ulonglong2 b1 = *(const ulonglong2*)&As[cur][kk][tx * 8 + 4];
            #pragma unroll
            for (int i = 0; i < 8; i++) {
                unsigned long long ad = pack2(a[i], a[i]);
                fma2(acc[i][0], ad, b0.x);
                fma2(acc[i][1], ad, b0.y);
                fma2(acc[i][2], ad, b1.x);
                fma2(acc[i][3], ad, b1.y);
            }
        }

        if (it < 31) {
            CP_WAIT0();
            const int nb = 1 - cur;
            As[nb][wc4 + 0][wo] = wreg.x; As[nb][wc4 + 1][wo] = wreg.y;
            As[nb][wc4 + 2][wo] = wreg.z; As[nb][wc4 + 3][wo] = wreg.w;
        }
        __syncthreads();
    }

    // epilogue
    float rr[8][8];
    float4 bi0 = *(const float4*)(bias + o0 + tx * 8);
    float4 bi1 = *(const float4*)(bias + o0 + tx * 8 + 4);
    const float bia[8] = {bi0.x, bi0.y, bi0.z, bi0.w, bi1.x, bi1.y, bi1.z, bi1.w};
    #pragma unroll
    for (int i = 0; i < 8; i++) {
        unpack2(acc[i][0], rr[i][0], rr[i][1]);
        unpack2(acc[i][1], rr[i][2], rr[i][3]);
        unpack2(acc[i][2], rr[i][4], rr[i][5]);
        unpack2(acc[i][3], rr[i][6], rr[i][7]);
        #pragma unroll
        for (int j = 0; j < 8; j++) rr[i][j] += bia[j];
    }
    #pragma unroll
    for (int i = 0; i < 8; i++) {
        const int n = n0 + ty * 8 + i;
        float* dst = g_Y + ((size_t)b * NN + n) * OC3 + o0 + tx * 8;
        *(float4*)dst       = make_float4(rr[i][0], rr[i][1], rr[i][2], rr[i][3]);
        *(float4*)(dst + 4) = make_float4(rr[i][4], rr[i][5], rr[i][6], rr[i][7]);
    }
    if (o0 >= CC && o0 < 2 * CC) {  // K slice -> transposed
        #pragma unroll
        for (int j = 0; j < 8; j++) {
            const int hd = o0 + tx * 8 + j - CC;
            float* dst = g_Kt + ((size_t)b * CC + hd) * NN + n0 + ty * 8;
            *(float4*)dst       = make_float4(rr[0][j], rr[1][j], rr[2][j], rr[3][j]);
            *(float4*)(dst + 4) = make_float4(rr[4][j], rr[5][j], rr[6][j], rr[7][j]);
        }
    }
}

// =====================================================================
// Kernel 2: flash attention. 64 q-rows per CTA, k-tile 128 (18 tiles),
// cp.async double-buffered K/V, 4q x 8k S microtile, 4q x 2d PV.
// Dynamic smem: Qs 8KB | Kts 2x16KB | Vs 2x16KB | Ps 32KB = 104KB.
// =====================================================================
__global__ __launch_bounds__(256, 2) void attn_kernel()
{
    extern __shared__ float sm[];
    float* Qs  = sm;                    // [64][32]
    float* Kts = sm + 2048;             // [2][32][128]
    float* Vs  = sm + 2048 + 8192;      // [2][128][32]
    float* Ps  = sm + 2048 + 16384;     // [64][128]
    const uint32_t smBase = sptr(sm);

    const int bh = blockIdx.y;
    const int b  = bh >> 3, h = bh & 7;
    const int q0 = blockIdx.x * 64;
    const int t  = threadIdx.x;
    const int tx = t & 15, ty = t >> 4;

    const float* Yb  = g_Y  + (size_t)b * NN * OC3;
    const float* Ktb = g_Kt + ((size_t)b * CC + h * HD) * NN;
    const float scale = 0.17677669529663689f;  // 1/sqrt(32)

    // issue preload of tile 0 into buffer 0
    {
        #pragma unroll
        for (int j = 0; j < 4; j++) {
            const int idx = j * 256 + t;
            const int kr = idx >> 5, kc = (idx & 31) << 2;
            CP_ASYNC16(smBase + (2048 + kr * 128 + kc) * 4, Ktb + (size_t)kr * NN + kc);
        }
        #pragma unroll
        for (int j = 0; j < 4; j++) {
            const int idx = j * 256 + t;
            const int vr = idx >> 3, vc = (idx & 7) << 2;
            CP_ASYNC16(smBase + (10240 + vr * 32 + vc) * 4,
                       Yb + (size_t)vr * OC3 + 2 * CC + h * HD + vc);
        }
        CP_COMMIT();
    }
    // load Q (scaled) while cp.async is in flight
    {
        const int r = t >> 2, c = (t & 3) << 3;
        const float* src = Yb + (size_t)(q0 + r) * OC3 + h * HD + c;
        float4 a = *(const float4*)src;
        float4 bq = *(const float4*)(src + 4);
        a.x *= scale; a.y *= scale; a.z *= scale; a.w *= scale;
        bq.x *= scale; bq.y *= scale; bq.z *= scale; bq.w *= scale;
        *(float4*)&Qs[r * 32 + c]     = a;
        *(float4*)&Qs[r * 32 + c + 4] = bq;
    }
    CP_WAIT0();
    __syncthreads();

    float m_i[4], l_i[4];
    unsigned long long o2[4];
    #pragma unroll
    for (int i = 0; i < 4; i++) { m_i[i] = -1e30f; l_i[i] = 0.0f; o2[i] = 0ULL; }

    #pragma unroll 1
    for (int kt = 0; kt < 18; kt++) {
        const int cur = kt & 1;
        if (kt < 17) {  // prefetch next tile into !cur
            const int k0n = (kt + 1) * 128;
            const uint32_t kdst = smBase + (2048 + (1 - cur) * 4096) * 4;
            const uint32_t vdst = smBase + (10240 + (1 - cur) * 4096) * 4;
            #pragma unroll
            for (int j = 0; j < 4; j++) {
                const int idx = j * 256 + t;
                const int kr = idx >> 5, kc = (idx & 31) << 2;
                CP_ASYNC16(kdst + (kr * 128 + kc) * 4, Ktb + (size_t)kr * NN + k0n + kc);
            }
            #pragma unroll
            for (int j = 0; j < 4; j++) {
                const int idx = j * 256 + t;
                const int vr = idx >> 3, vc = (idx & 7) << 2;
                CP_ASYNC16(vdst + (vr * 32 + vc) * 4,
                           Yb + (size_t)(k0n + vr) * OC3 + 2 * CC + h * HD + vc);
            }
            CP_COMMIT();
        }

        // ---- S = Q K^T ----
        const float* Kb = Kts + cur * 4096;
        unsigned long long sA[4][4];
        #pragma unroll
        for (int i = 0; i < 4; i++)
            #pragma unroll
            for (int j = 0; j < 4; j++) sA[i][j] = 0ULL;

        #pragma unroll
        for (int d4 = 0; d4 < 32; d4 += 4) {
            float a[4][4];
            #pragma unroll
            for (int i = 0; i < 4; i++)
                *(float4*)&a[i][0] = *(const float4*)&Qs[(ty * 4 + i) * 32 + d4];
            #pragma unroll
            for (int u = 0; u < 4; u++) {
                ulonglong2 k0v = *(const ulonglong2*)&Kb[(d4 + u) * 128 + tx * 8];
                ulonglong2 k1v = *(const ulonglong2*)&Kb[(d4 + u) * 128 + tx * 8 + 4];
                #pragma unroll
                for (int i = 0; i < 4; i++) {
                    unsigned long long ad = pack2(a[i][u], a[i][u]);
                    fma2(sA[i][0], ad, k0v.x);
                    fma2(sA[i][1], ad, k0v.y);
                    fma2(sA[i][2], ad, k1v.x);
                    fma2(sA[i][3], ad, k1v.y);
                }
            }
        }

        // ---- online softmax (row = 16 tx lanes) ----
        #pragma unroll
        for (int i = 0; i < 4; i++) {
            float s[8];
            unpack2(sA[i][0], s[0], s[1]);
            unpack2(sA[i][1], s[2], s[3]);
            unpack2(sA[i][2], s[4], s[5]);
            unpack2(sA[i][3], s[6], s[7]);
            float mx = fmaxf(fmaxf(fmaxf(s[0], s[1]), fmaxf(s[2], s[3])),
                             fmaxf(fmaxf(s[4], s[5]), fmaxf(s[6], s[7])));
            #pragma unroll
            for (int msk = 8; msk >= 1; msk >>= 1)
                mx = fmaxf(mx, __shfl_xor_sync(0xffffffffu, mx, msk));
            const float mnew = fmaxf(m_i[i], mx);
            float p[8], rs = 0.0f;
            #pragma unroll
            for (int j = 0; j < 8; j++) { p[j] = __expf(s[j] - mnew); rs += p[j]; }
            #pragma unroll
            for (int msk = 8; msk >= 1; msk >>= 1)
                rs += __shfl_xor_sync(0xffffffffu, rs, msk);
            const float alpha = __expf(m_i[i] - mnew);
            l_i[i] = l_i[i] * alpha + rs;
            m_i[i] = mnew;
            o2[i]  = mul2(o2[i], pack2(alpha, alpha));
            float* pr = Ps + (ty * 4 + i) * 128 + tx * 8;
            *(float4*)pr       = make_float4(p[0], p[1], p[2], p[3]);
            *(float4*)(pr + 4) = make_float4(p[4], p[5], p[6], p[7]);
        }
        __syncthreads();  // Ps visible

        // ---- O += P V ----
        const float* Vb = Vs + cur * 4096;
        #pragma unroll 8
        for (int m4 = 0; m4 < 128; m4 += 4) {
            float pa[4][4];
            #pragma unroll
            for (int i = 0; i < 4; i++)
                *(float4*)&pa[i][0] = *(const float4*)&Ps[(ty * 4 + i) * 128 + m4];
            #pragma unroll
            for (int u = 0; u < 4; u++) {
                unsigned long long v = *(const unsigned long long*)&Vb[(m4 + u) * 32 + tx * 2];
                #pragma unroll
                for (int i = 0; i < 4; i++)
                    fma2(o2[i], pack2(pa[i][u], pa[i][u]), v);
            }
        }

        CP_WAIT0();
        __syncthreads();  // next buffers visible + Ps protect
    }

    // finalize
    #pragma unroll
    for (int i = 0; i < 4; i++) {
        const float inv = 1.0f / l_i[i];
        float x0, x1;
        unpack2(o2[i], x0, x1);
        const int n = q0 + ty * 4 + i;
        *(float2*)(g_O + ((size_t)b * NN + n) * CC + h * HD + tx * 2)
            = make_float2(x0 * inv, x1 * inv);
    }
}

// =====================================================================
// Kernel 3: proj + bias + residual. Tile 128n x 64c, Kc=8, 8x4 microtile.
// =====================================================================
__global__ __launch_bounds__(256, 2) void proj_kernel(
    const float* __restrict__ X, const float* __restrict__ Wp,
    const float* __restrict__ bp, float* __restrict__ out)
{
    __shared__ float As[2][8][64];   // [p][c]
    __shared__ float Bs[2][8][128];  // [p][n]

    const int b  = blockIdx.z;
    const int n0 = blockIdx.x * 128;
    const int c0 = blockIdx.y * 64;
    const int t  = threadIdx.x;
    const int tx = t & 15, ty = t >> 4;

    const float* Ob = g_O + (size_t)b * NN * CC;

    // loaders: As (t<128): c row, p col4 ; Bs: n row, p col4
    const int wr  = t & 63,  wp4 = ((t >> 6) & 1) << 2;   // valid when t<128
    const int nr  = t & 127, pb4 = (t >> 7) << 2;

    unsigned long long acc[8][2];
    #pragma unroll
    for (int i = 0; i < 8; i++) { acc[i][0] = 0ULL; acc[i][1] = 0ULL; }

    float4 wv = make_float4(0, 0, 0, 0), ov;
    if (t < 128) wv = *(const float4*)(Wp + (size_t)(c0 + wr) * CC + wp4);
    ov = *(const float4*)(Ob + (size_t)(n0 + nr) * CC + pb4);
    {
        if (t < 128) {
            As[0][wp4 + 0][wr] = wv.x; As[0][wp4 + 1][wr] = wv.y;
            As[0][wp4 + 2][wr] = wv.z; As[0][wp4 + 3][wr] = wv.w;
        }
        Bs[0][pb4 + 0][nr] = ov.x; Bs[0][pb4 + 1][nr] = ov.y;
        Bs[0][pb4 + 2][nr] = ov.z; Bs[0][pb4 + 3][nr] = ov.w;
    }
    __syncthreads();

    #pragma unroll 1
    for (int it = 0; it < 32; it++) {
        const int cur = it & 1;
        if (it < 31) {
            const int p0 = (it + 1) * 8;
            if (t < 128) wv = *(const float4*)(Wp + (size_t)(c0 + wr) * CC + p0 + wp4);
            ov = *(const float4*)(Ob + (size_t)(n0 + nr) * CC + p0 + pb4);
        }

        #pragma unroll
        for (int kk = 0; kk < 8; kk++) {
            float a[8];
            *(float4*)&a[0] = *(const float4*)&Bs[cur][kk][ty * 8];
            *(float4*)&a[4] = *(const float4*)&Bs[cur][kk][ty * 8 + 4];
            ulonglong2 bb = *(const ulonglong2*)&As[cur][kk][tx * 4];
            #pragma unroll
            for (int i = 0; i < 8; i++) {
                unsigned long long ad = pack2(a[i], a[i]);
                fma2(acc[i][0], ad, bb.x);
                fma2(acc[i][1], ad, bb.y);
            }
        }

        if (it < 31) {
            const int nb = 1 - cur;
            if (t < 128) {
                As[nb][wp4 + 0][wr] = wv.x; As[nb][wp4 + 1][wr] = wv.y;
                As[nb][wp4 + 2][wr] = wv.z; As[nb][wp4 + 3][wr] = wv.w;
            }
            Bs[nb][pb4 + 0][nr] = ov.x; Bs[nb][pb4 + 1][nr] = ov.y;
            Bs[nb][pb4 + 2][nr] = ov.z; Bs[nb][pb4 + 3][nr] = ov.w;
        }
        __syncthreads();
    }

    // epilogue: transpose in regs, add bias + residual, write [c][n]
    float rr[8][4];
    #pragma unroll
    for (int i = 0; i < 8; i++) {
        unpack2(acc[i][0], rr[i][0], rr[i][1]);
        unpack2(acc[i][1], rr[i][2], rr[i][3]);
    }
    const float* Xb = X + (size_t)b * CC * NN;
    #pragma unroll
    for (int j = 0; j < 4; j++) {
        const int c = c0 + tx * 4 + j;
        const float bi = bp[c];
        const float* xs = Xb + (size_t)c * NN + n0 + ty * 8;
        float4 x0 = *(const float4*)xs;
        float4 x1 = *(const float4*)(xs + 4);
        float4 r0 = make_float4(rr[0][j] + bi + x0.x, rr[1][j] + bi + x0.y,
                                rr[2][j] + bi + x0.z, rr[3][j] + bi + x0.w);
        float4 r1 = make_float4(rr[4][j] + bi + x1.x, rr[5][j] + bi + x1.y,
                                rr[6][j] + bi + x1.z, rr[7][j] + bi + x1.w);
        float* dst = out + (size_t)b * CC * NN + (size_t)c * NN + n0 + ty * 8;
        *(float4*)dst       = r0;
        *(float4*)(dst + 4) = r1;
    }
}

// =====================================================================
extern "C" void kernel_launch(void* const* d_in, const int* in_sizes, int n_in,
                              void* d_out, int out_size)
{
    const float* x      = (const float*)d_in[0];
    const float* w_qkv  = (const float*)d_in[1];
    const float* b_qkv  = (const float*)d_in[2];
    const float* w_proj = (const float*)d_in[3];
    const float* b_proj = (const float*)d_in[4];
    float* out = (float*)d_out;

    const int attn_smem = (2048 + 8192 + 8192 + 8192) * 4;  // 106496 B
    cudaFuncSetAttribute(attn_kernel, cudaFuncAttributeMaxDynamicSharedMemorySize, attn_smem);

    qkv_kernel <<<dim3(NN / 128, OC3 / 128, BB), 256>>>(x, w_qkv, b_qkv);
    attn_kernel<<<dim3(NN / 64, BB * NH, 1), 256, attn_smem>>>();
    proj_kernel<<<dim3(NN / 128, CC / 64, BB), 256>>>(x, w_proj, b_proj, out);
}

// round 3
// speedup vs baseline: 2.2123x; 2.2123x over previous
#include <cuda_runtime.h>
#include <cuda_bf16.h>
#include <cstdint>

#define BB   2
#define CC   256
#define NN   2304
#define OC3  768
#define NH   8
#define HD   32
#define NBH  (BB*NH)

// Scratch (device globals — allocation-free)
__device__ float g_Y[BB * NN * OC3];                         // qkv out [b][n][768]
__device__ float g_O[BB * NN * CC];                          // attn out [b][n][c]
__device__ __align__(16) uint32_t g_KPh[NBH * NN * (HD/2)];  // K bf16 hi pairs [bh][n][d/2]
__device__ __align__(16) uint32_t g_KPl[NBH * NN * (HD/2)];
__device__ __align__(16) uint32_t g_VPh[NBH * HD * (NN/2)];  // V^T bf16 hi pairs [bh][d][n/2]
__device__ __align__(16) uint32_t g_VPl[NBH * HD * (NN/2)];

// ---------- packed f32x2 helpers (for qkv/proj fp32 GEMMs) ----------
__device__ __forceinline__ unsigned long long pack2(float x, float y) {
    unsigned long long r;
    asm("mov.b64 %0, {%1, %2};" : "=l"(r) : "f"(x), "f"(y));
    return r;
}
__device__ __forceinline__ void unpack2(unsigned long long v, float& x, float& y) {
    asm("mov.b64 {%0, %1}, %2;" : "=f"(x), "=f"(y) : "l"(v));
}
__device__ __forceinline__ void fma2(unsigned long long& d, unsigned long long a, unsigned long long b) {
    asm("fma.rn.f32x2 %0, %1, %2, %3;" : "=l"(d) : "l"(a), "l"(b), "l"(d));
}

// ---------- bf16 split helpers ----------
__device__ __forceinline__ uint32_t bf2_pack(float lo_elem, float hi_elem) {
    // returns bf16x2 with low half = lo_elem, high half = hi_elem
    uint32_t d;
    asm("cvt.rn.bf16x2.f32 %0, %1, %2;" : "=r"(d) : "f"(hi_elem), "f"(lo_elem));
    return d;
}
__device__ __forceinline__ float2 bf2_unpack(uint32_t v) {
    __nv_bfloat162 h;
    *reinterpret_cast<uint32_t*>(&h) = v;
    return __bfloat1622float2(h);
}
__device__ __forceinline__ void split2(float x, float y, uint32_t& hi, uint32_t& lo) {
    hi = bf2_pack(x, y);
    float2 f = bf2_unpack(hi);
    lo = bf2_pack(x - f.x, y - f.y);
}

// ---------- mma.sync m16n8k16 bf16 ----------
__device__ __forceinline__ void mma16816(float c[4], const uint32_t a[4], uint32_t b0, uint32_t b1) {
    asm volatile(
        "mma.sync.aligned.m16n8k16.row.col.f32.bf16.bf16.f32 "
        "{%0,%1,%2,%3}, {%4,%5,%6,%7}, {%8,%9}, {%0,%1,%2,%3};"
        : "+f"(c[0]), "+f"(c[1]), "+f"(c[2]), "+f"(c[3])
        : "r"(a[0]), "r"(a[1]), "r"(a[2]), "r"(a[3]), "r"(b0), "r"(b1));
}

// ---------- cp.async ----------
#define CP_ASYNC16(dst, src) \
    asm volatile("cp.async.cg.shared.global [%0], [%1], 16;" :: "r"(dst), "l"(src))
#define CP_COMMIT() asm volatile("cp.async.commit_group;")
#define CP_WAIT0()  asm volatile("cp.async.wait_group 0;" ::: "memory")
__device__ __forceinline__ uint32_t sptr(const void* p) {
    return (uint32_t)__cvta_generic_to_shared(p);
}

// =====================================================================
// Kernel 1: QKV GEMM (R1 version) + split-bf16 K/V packing epilogue.
//   Y[b][n][o] = sum_c W[o][c] X[b][c][n] + bias[o]
// =====================================================================
__global__ __launch_bounds__(256) void qkv_kernel(
    const float* __restrict__ X, const float* __restrict__ W,
    const float* __restrict__ bias)
{
    __shared__ float As[16][64];  // [c][o]
    __shared__ float Bs[16][64];  // [c][n]

    const int b  = blockIdx.z;
    const int n0 = blockIdx.x * 64;
    const int o0 = blockIdx.y * 64;
    const int t  = threadIdx.x;
    const int tx = t & 15, ty = t >> 4;

    const float* Xb = X + (size_t)b * CC * NN;

    const int wo = t >> 2,  wc = (t & 3) << 2;
    const int xc = t >> 4,  xn = (t & 15) << 2;

    unsigned long long cacc[4][2];
    #pragma unroll
    for (int i = 0; i < 4; i++) { cacc[i][0] = 0ULL; cacc[i][1] = 0ULL; }

    for (int c0 = 0; c0 < CC; c0 += 16) {
        float4 w4 = *(const float4*)(W + (size_t)(o0 + wo) * CC + c0 + wc);
        As[wc + 0][wo] = w4.x; As[wc + 1][wo] = w4.y;
        As[wc + 2][wo] = w4.z; As[wc + 3][wo] = w4.w;
        *(float4*)&Bs[xc][xn] = *(const float4*)(Xb + (size_t)(c0 + xc) * NN + n0 + xn);
        __syncthreads();

        #pragma unroll
        for (int kk = 0; kk < 16; kk++) {
            float4 a4 = *(const float4*)&Bs[kk][ty << 2];
            ulonglong2 b2 = *(const ulonglong2*)&As[kk][tx << 2];
            float a[4] = {a4.x, a4.y, a4.z, a4.w};
            #pragma unroll
            for (int i = 0; i < 4; i++) {
                unsigned long long ad = pack2(a[i], a[i]);
                fma2(cacc[i][0], ad, b2.x);
                fma2(cacc[i][1], ad, b2.y);
            }
        }
        __syncthreads();
    }

    float4 bi4 = *(const float4*)(bias + o0 + (tx << 2));
    const int obase = o0 + (tx << 2);

    float rr[4][4];
    #pragma unroll
    for (int i = 0; i < 4; i++) {
        unpack2(cacc[i][0], rr[i][0], rr[i][1]);
        unpack2(cacc[i][1], rr[i][2], rr[i][3]);
        rr[i][0] += bi4.x; rr[i][1] += bi4.y;
        rr[i][2] += bi4.z; rr[i][3] += bi4.w;
        const int n = n0 + (ty << 2) + i;
        *(float4*)(g_Y + ((size_t)b * NN + n) * OC3 + obase)
            = make_float4(rr[i][0], rr[i][1], rr[i][2], rr[i][3]);
    }

    if (obase >= CC && obase < 2 * CC) {
        // K slice: write bf16 hi/lo pairs along d, layout [bh][n][d/2]
        const int d  = obase - CC;          // 0..255 = h*32 + dd
        const int bh = b * NH + (d >> 5);
        const int ddw = (d & 31) >> 1;      // word index (pairs of d)
        #pragma unroll
        for (int i = 0; i < 4; i++) {
            const int n = n0 + (ty << 2) + i;
            uint32_t h0, l0, h1, l1;
            split2(rr[i][0], rr[i][1], h0, l0);
            split2(rr[i][2], rr[i][3], h1, l1);
            uint32_t* dh = g_KPh + ((size_t)bh * NN + n) * (HD/2) + ddw;
            uint32_t* dl = g_KPl + ((size_t)bh * NN + n) * (HD/2) + ddw;
            dh[0] = h0; dh[1] = h1;
            dl[0] = l0; dl[1] = l1;
        }
    } else if (obase >= 2 * CC) {
        // V slice: write bf16 hi/lo pairs along n, layout [bh][d][n/2]
        const int d  = obase - 2 * CC;
        const int bh = b * NH + (d >> 5);
        const int np = (n0 + (ty << 2)) >> 1;
        #pragma unroll
        for (int j = 0; j < 4; j++) {
            const int dd = (d & 31) + j;
            uint32_t h0, l0, h1, l1;
            split2(rr[0][j], rr[1][j], h0, l0);
            split2(rr[2][j], rr[3][j], h1, l1);
            uint32_t* dh = g_VPh + ((size_t)bh * HD + dd) * (NN/2) + np;
            uint32_t* dl = g_VPl + ((size_t)bh * HD + dd) * (NN/2) + np;
            dh[0] = h0; dh[1] = h1;
            dl[0] = l0; dl[1] = l1;
        }
    }
}

// =====================================================================
// Kernel 2: flash attention with mma.sync bf16, 3-product fp32 emulation.
//   grid (18 q-tiles, 16 bh), 256 threads; warp w owns q rows [w*16,w*16+16).
//   k-tile 128, double-buffered cp.async of pre-split K/V.
// smem (words): KPh[2][2560] KPl[2][2560] VPh[2][2176] VPl[2][2176] = 75776 B
// =====================================================================
#define KS 2560   // 128 rows * 20 (16 data words + 4 pad)
#define VS 2176   // 32 rows * 68 (64 data words + 4 pad)

__global__ __launch_bounds__(256) void attn_kernel()
{
    extern __shared__ uint32_t sm[];
    uint32_t* sKh = sm;
    uint32_t* sKl = sm + 2 * KS;
    uint32_t* sVh = sm + 4 * KS;
    uint32_t* sVl = sm + 4 * KS + 2 * VS;

    const int bh = blockIdx.y;
    const int b  = bh >> 3, h = bh & 7;
    const int q0 = blockIdx.x * 128;
    const int t  = threadIdx.x;
    const int wid = t >> 5, lane = t & 31;
    const int gr = lane >> 2, gc = lane & 3;

    const uint32_t* gKh = g_KPh + (size_t)bh * NN * (HD/2);
    const uint32_t* gKl = g_KPl + (size_t)bh * NN * (HD/2);
    const uint32_t* gVh = g_VPh + (size_t)bh * HD * (NN/2);
    const uint32_t* gVl = g_VPl + (size_t)bh * HD * (NN/2);

    // ---- Q a-fragments (scaled, split hi/lo), loaded once from g_Y ----
    uint32_t aQh[2][4], aQl[2][4];
    {
        const float scale = 0.17677669529663689f;  // 1/sqrt(32)
        const float* Qb = g_Y + ((size_t)b * NN + q0 + wid * 16) * OC3 + h * HD;
        #pragma unroll
        for (int ks = 0; ks < 2; ks++) {
            #pragma unroll
            for (int p = 0; p < 4; p++) {
                const int row = gr + ((p & 1) ? 8 : 0);
                const int col = 2 * gc + ((p & 2) ? 8 : 0) + ks * 16;
                float2 q = *(const float2*)(Qb + (size_t)row * OC3 + col);
                q.x *= scale; q.y *= scale;
                split2(q.x, q.y, aQh[ks][p], aQl[ks][p]);
            }
        }
    }

    // ---- tile loader (cp.async, 8 chunks of 16B per thread) ----
    auto load_tile = [&](int k0, int s) {
        #pragma unroll
        for (int j = 0; j < 4; j++) {                       // K: 1024 chunks
            const int idx = j * 256 + t;
            const int arr = idx >> 9;
            const int rem = idx & 511;
            const int r = rem >> 2, ch = (rem & 3) << 2;
            const uint32_t* src = (arr ? gKl : gKh) + (size_t)(k0 + r) * (HD/2) + ch;
            uint32_t dst = sptr((arr ? sKl : sKh) + s * KS + r * 20 + ch);
            CP_ASYNC16(dst, src);
        }
        #pragma unroll
        for (int j = 0; j < 4; j++) {                       // V: 1024 chunks
            const int idx = j * 256 + t;
            const int arr = idx >> 9;
            const int rem = idx & 511;
            const int r = rem >> 4, ch = (rem & 15) << 2;
            const uint32_t* src = (arr ? gVl : gVh) + (size_t)r * (NN/2) + (k0 >> 1) + ch;
            uint32_t dst = sptr((arr ? sVl : sVh) + s * VS + r * 68 + ch);
            CP_ASYNC16(dst, src);
        }
    };

    float m_[2] = {-1e30f, -1e30f};
    float l_[2] = {0.0f, 0.0f};
    float o[4][4];
    #pragma unroll
    for (int nv = 0; nv < 4; nv++)
        #pragma unroll
        for (int k = 0; k < 4; k++) o[nv][k] = 0.0f;

    load_tile(0, 0);
    CP_COMMIT();
    CP_WAIT0();
    __syncthreads();

    #pragma unroll 1
    for (int kt = 0; kt < 18; kt++) {
        const int cur = kt & 1;
        if (kt < 17) { load_tile((kt + 1) * 128, 1 - cur); CP_COMMIT(); }

        // ---- S = Q K^T (3-product split) ----
        float c[16][4];
        #pragma unroll
        for (int nf = 0; nf < 16; nf++)
            #pragma unroll
            for (int k = 0; k < 4; k++) c[nf][k] = 0.0f;

        const uint32_t* Kh = sKh + cur * KS;
        const uint32_t* Kl = sKl + cur * KS;
        #pragma unroll
        for (int nf = 0; nf < 16; nf++) {
            const int base = (nf * 8 + gr) * 20;
            #pragma unroll
            for (int ks = 0; ks < 2; ks++) {
                const uint32_t bh0 = Kh[base + ks * 8 + gc];
                const uint32_t bh1 = Kh[base + ks * 8 + 4 + gc];
                const uint32_t bl0 = Kl[base + ks * 8 + gc];
                const uint32_t bl1 = Kl[base + ks * 8 + 4 + gc];
                mma16816(c[nf], aQh[ks], bh0, bh1);
                mma16816(c[nf], aQl[ks], bh0, bh1);
                mma16816(c[nf], aQh[ks], bl0, bl1);
            }
        }

        // ---- online softmax (rows warp-local; reduce over 4 gc lanes) ----
        float mx0 = -1e30f, mx1 = -1e30f;
        #pragma unroll
        for (int nf = 0; nf < 16; nf++) {
            mx0 = fmaxf(mx0, fmaxf(c[nf][0], c[nf][1]));
            mx1 = fmaxf(mx1, fmaxf(c[nf][2], c[nf][3]));
        }
        mx0 = fmaxf(mx0, __shfl_xor_sync(0xffffffffu, mx0, 1));
        mx0 = fmaxf(mx0, __shfl_xor_sync(0xffffffffu, mx0, 2));
        mx1 = fmaxf(mx1, __shfl_xor_sync(0xffffffffu, mx1, 1));
        mx1 = fmaxf(mx1, __shfl_xor_sync(0xffffffffu, mx1, 2));
        const float mn0 = fmaxf(m_[0], mx0);
        const float mn1 = fmaxf(m_[1], mx1);
        const float al0 = __expf(m_[0] - mn0);
        const float al1 = __expf(m_[1] - mn1);
        m_[0] = mn0; m_[1] = mn1;

        float s0 = 0.0f, s1 = 0.0f;
        #pragma unroll
        for (int nf = 0; nf < 16; nf++) {
            c[nf][0] = __expf(c[nf][0] - mn0);
            c[nf][1] = __expf(c[nf][1] - mn0);
            c[nf][2] = __expf(c[nf][2] - mn1);
            c[nf][3] = __expf(c[nf][3] - mn1);
            s0 += c[nf][0] + c[nf][1];
            s1 += c[nf][2] + c[nf][3];
        }
        s0 += __shfl_xor_sync(0xffffffffu, s0, 1);
        s0 += __shfl_xor_sync(0xffffffffu, s0, 2);
        s1 += __shfl_xor_sync(0xffffffffu, s1, 1);
        s1 += __shfl_xor_sync(0xffffffffu, s1, 2);
        l_[0] = l_[0] * al0 + s0;
        l_[1] = l_[1] * al1 + s1;

        #pragma unroll
        for (int nv = 0; nv < 4; nv++) {
            o[nv][0] *= al0; o[nv][1] *= al0;
            o[nv][2] *= al1; o[nv][3] *= al1;
        }

        // ---- O += P V (3-product split; P repacked from c in-regs) ----
        const uint32_t* Vh = sVh + cur * VS;
        const uint32_t* Vl = sVl + cur * VS;
        #pragma unroll
        for (int j = 0; j < 8; j++) {
            uint32_t pAh[4], pAl[4];
            split2(c[2*j][0],   c[2*j][1],   pAh[0], pAl[0]);
            split2(c[2*j][2],   c[2*j][3],   pAh[1], pAl[1]);
            split2(c[2*j+1][0], c[2*j+1][1], pAh[2], pAl[2]);
            split2(c[2*j+1][2], c[2*j+1][3], pAh[3], pAl[3]);
            #pragma unroll
            for (int nv = 0; nv < 4; nv++) {
                const int vb = (nv * 8 + gr) * 68 + j * 8;
                const uint32_t vh0 = Vh[vb + gc],     vh1 = Vh[vb + 4 + gc];
                const uint32_t vl0 = Vl[vb + gc],     vl1 = Vl[vb + 4 + gc];
                mma16816(o[nv], pAh, vh0, vh1);
                mma16816(o[nv], pAl, vh0, vh1);
                mma16816(o[nv], pAh, vl0, vl1);
            }
        }

        CP_WAIT0();
        __syncthreads();
    }

    // ---- finalize ----
    const float inv0 = 1.0f / l_[0];
    const float inv1 = 1.0f / l_[1];
    const int r0 = q0 + wid * 16 + gr;
    const int r1 = r0 + 8;
    float* Ob = g_O + (size_t)b * NN * CC + h * HD;
    #pragma unroll
    for (int nv = 0; nv < 4; nv++) {
        *(float2*)(Ob + (size_t)r0 * CC + nv * 8 + 2 * gc)
            = make_float2(o[nv][0] * inv0, o[nv][1] * inv0);
        *(float2*)(Ob + (size_t)r1 * CC + nv * 8 + 2 * gc)
            = make_float2(o[nv][2] * inv1, o[nv][3] * inv1);
    }
}

// =====================================================================
// Kernel 3: proj + bias + residual (R1 version).
// =====================================================================
__global__ __launch_bounds__(256) void proj_kernel(
    const float* __restrict__ X, const float* __restrict__ Wp,
    const float* __restrict__ bp, float* __restrict__ out)
{
    __shared__ float As[16][64];  // [c'][c]
    __shared__ float Bs[16][64];  // [c'][n]

    const int b  = blockIdx.z;
    const int n0 = blockIdx.x * 64;
    const int c0 = blockIdx.y * 64;
    const int t  = threadIdx.x;
    const int tx = t & 15, ty = t >> 4;

    const float* Ob = g_O + (size_t)b * NN * CC;
    const int wr = t >> 2, wc = (t & 3) << 2;

    unsigned long long cacc[4][2];
    #pragma unroll
    for (int i = 0; i < 4; i++) { cacc[i][0] = 0ULL; cacc[i][1] = 0ULL; }

    for (int p0 = 0; p0 < CC; p0 += 16) {
        float4 w4 = *(const float4*)(Wp + (size_t)(c0 + wr) * CC + p0 + wc);
        As[wc + 0][wr] = w4.x; As[wc + 1][wr] = w4.y;
        As[wc + 2][wr] = w4.z; As[wc + 3][wr] = w4.w;
        float4 o4 = *(const float4*)(Ob + (size_t)(n0 + wr) * CC + p0 + wc);
        Bs[wc + 0][wr] = o4.x; Bs[wc + 1][wr] = o4.y;
        Bs[wc + 2][wr] = o4.z; Bs[wc + 3][wr] = o4.w;
        __syncthreads();

        #pragma unroll
        for (int kk = 0; kk < 16; kk++) {
            float4 a4 = *(const float4*)&As[kk][ty << 2];
            ulonglong2 b2 = *(const ulonglong2*)&Bs[kk][tx << 2];
            float a[4] = {a4.x, a4.y, a4.z, a4.w};
            #pragma unroll
            for (int i = 0; i < 4; i++) {
                unsigned long long ad = pack2(a[i], a[i]);
                fma2(cacc[i][0], ad, b2.x);
                fma2(cacc[i][1], ad, b2.y);
            }
        }
        __syncthreads();
    }

    const float* Xb = X + (size_t)b * CC * NN;
    #pragma unroll
    for (int i = 0; i < 4; i++) {
        const int c = c0 + (ty << 2) + i;
        const float bi = bp[c];
        float4 x4 = *(const float4*)(Xb + (size_t)c * NN + n0 + (tx << 2));
        float r0, r1, r2, r3;
        unpack2(cacc[i][0], r0, r1);
        unpack2(cacc[i][1], r2, r3);
        float4 r;
        r.x = r0 + bi + x4.x; r.y = r1 + bi + x4.y;
        r.z = r2 + bi + x4.z; r.w = r3 + bi + x4.w;
        *(float4*)(out + (size_t)b * CC * NN + (size_t)c * NN + n0 + (tx << 2)) = r;
    }
}

// =====================================================================
extern "C" void kernel_launch(void* const* d_in, const int* in_sizes, int n_in,
                              void* d_out, int out_size)
{
    const float* x      = (const float*)d_in[0];
    const float* w_qkv  = (const float*)d_in[1];
    const float* b_qkv  = (const float*)d_in[2];
    const float* w_proj = (const float*)d_in[3];
    const float* b_proj = (const float*)d_in[4];
    float* out = (float*)d_out;

    const int attn_smem = (4 * KS + 4 * VS) * 4;  // 75776 B
    cudaFuncSetAttribute(attn_kernel, cudaFuncAttributeMaxDynamicSharedMemorySize, attn_smem);

    qkv_kernel <<<dim3(NN / 64, OC3 / 64, BB), 256>>>(x, w_qkv, b_qkv);
    attn_kernel<<<dim3(NN / 128, NBH, 1), 256, attn_smem>>>();
    proj_kernel<<<dim3(NN / 64, CC / 64, BB), 256>>>(x, w_proj, b_proj, out);
}

// round 4
// speedup vs baseline: 2.4788x; 1.1204x over previous
#include <cuda_runtime.h>
#include <cuda_bf16.h>
#include <cstdint>

#define BB   2
#define CC   256
#define NN   2304
#define OC3  768
#define NH   8
#define HD   32
#define NBH  (BB*NH)
#define NG   (BB*NN)     // 4608 flattened (b,n)

// ---------------- device scratch ----------------
__device__ float g_Q[NG * CC];                               // Q fp32 [ng][c]
__device__ __align__(16) uint32_t g_XPh[NG * 128];           // X split pairs along c [ng][c/2]
__device__ __align__(16) uint32_t g_XPl[NG * 128];
__device__ __align__(16) uint32_t g_WqPh[OC3 * 128];         // W_qkv split [o][c/2]
__device__ __align__(16) uint32_t g_WqPl[OC3 * 128];
__device__ __align__(16) uint32_t g_WpPh[CC * 128];          // W_proj split [c][c'/2]
__device__ __align__(16) uint32_t g_WpPl[CC * 128];
__device__ __align__(16) uint32_t g_KPh[NBH * NN * (HD/2)];  // K pairs along d [bh][n][d/2]
__device__ __align__(16) uint32_t g_KPl[NBH * NN * (HD/2)];
__device__ __align__(16) uint32_t g_VPh[NBH * HD * (NN/2)];  // V^T pairs along n [bh][d][n/2]
__device__ __align__(16) uint32_t g_VPl[NBH * HD * (NN/2)];
__device__ __align__(16) uint32_t g_OPh[NG * 128];           // attn out split [ng][c/2]
__device__ __align__(16) uint32_t g_OPl[NG * 128];

// ---------------- helpers ----------------
__device__ __forceinline__ uint32_t bf2_pack(float lo_elem, float hi_elem) {
    uint32_t d;
    asm("cvt.rn.bf16x2.f32 %0, %1, %2;" : "=r"(d) : "f"(hi_elem), "f"(lo_elem));
    return d;
}
__device__ __forceinline__ float2 bf2_unpack(uint32_t v) {
    __nv_bfloat162 h;
    *reinterpret_cast<uint32_t*>(&h) = v;
    return __bfloat1622float2(h);
}
__device__ __forceinline__ void split2(float x, float y, uint32_t& hi, uint32_t& lo) {
    hi = bf2_pack(x, y);
    float2 f = bf2_unpack(hi);
    lo = bf2_pack(x - f.x, y - f.y);
}
__device__ __forceinline__ void mma16816(float c[4], const uint32_t a[4], uint32_t b0, uint32_t b1) {
    asm volatile(
        "mma.sync.aligned.m16n8k16.row.col.f32.bf16.bf16.f32 "
        "{%0,%1,%2,%3}, {%4,%5,%6,%7}, {%8,%9}, {%0,%1,%2,%3};"
        : "+f"(c[0]), "+f"(c[1]), "+f"(c[2]), "+f"(c[3])
        : "r"(a[0]), "r"(a[1]), "r"(a[2]), "r"(a[3]), "r"(b0), "r"(b1));
}
#define CP_ASYNC16(dst, src) \
    asm volatile("cp.async.cg.shared.global [%0], [%1], 16;" :: "r"(dst), "l"(src))
#define CP_COMMIT() asm volatile("cp.async.commit_group;")
#define CP_WAIT0()  asm volatile("cp.async.wait_group 0;" ::: "memory")
__device__ __forceinline__ uint32_t sptr(const void* p) {
    return (uint32_t)__cvta_generic_to_shared(p);
}

// =====================================================================
// Prep A: split weights into bf16x2 hi/lo words (pairs along input chan).
// =====================================================================
__global__ __launch_bounds__(256) void split_w_kernel(
    const float* __restrict__ Wq, const float* __restrict__ Wp)
{
    const int idx = blockIdx.x * 256 + threadIdx.x;  // 131072 total
    const int r = idx >> 7, w = idx & 127;
    if (r < OC3) {
        float2 f = *(const float2*)(Wq + (size_t)r * CC + 2 * w);
        uint32_t hi, lo;
        split2(f.x, f.y, hi, lo);
        g_WqPh[r * 128 + w] = hi;
        g_WqPl[r * 128 + w] = lo;
    } else {
        const int rr = r - OC3;
        float2 f = *(const float2*)(Wp + (size_t)rr * CC + 2 * w);
        uint32_t hi, lo;
        split2(f.x, f.y, hi, lo);
        g_WpPh[rr * 128 + w] = hi;
        g_WpPl[rr * 128 + w] = lo;
    }
}

// =====================================================================
// Prep B: transpose-split X [b][c][n] -> pairs along c, [ng][c/2].
// =====================================================================
__global__ __launch_bounds__(256) void split_x_kernel(const float* __restrict__ X)
{
    __shared__ float s[64][65];
    const int b  = blockIdx.z;
    const int c0 = blockIdx.y * 64;
    const int n0 = blockIdx.x * 64;
    const int t  = threadIdx.x;

    #pragma unroll
    for (int j = 0; j < 16; j++) {
        const int idx = j * 256 + t;
        const int r = idx >> 6, col = idx & 63;
        s[r][col] = X[(size_t)b * CC * NN + (size_t)(c0 + r) * NN + n0 + col];
    }
    __syncthreads();
    #pragma unroll
    for (int j = 0; j < 8; j++) {
        const int idx = j * 256 + t;
        const int nl = idx >> 5, w = idx & 31;
        uint32_t hi, lo;
        split2(s[2 * w][nl], s[2 * w + 1][nl], hi, lo);
        const size_t o = ((size_t)b * NN + n0 + nl) * 128 + (c0 >> 1) + w;
        g_XPh[o] = hi;
        g_XPl[o] = lo;
    }
}

// =====================================================================
// Shared GEMM mainloop macro pieces (128M x 128N CTA, K=256, chunk 32).
// smem: 8 arrays of [128][20] words x2 stages = 81920 B (reused by epilogue).
// =====================================================================
#define STRD 20
#define STGW (128 * STRD)

#define GEMM_MAINLOOP(AH, AL, BH, BL, M0, N0G)                                      \
    uint32_t* sAh = smw;                                                            \
    uint32_t* sAl = smw + 2 * STGW;                                                 \
    uint32_t* sBh = smw + 4 * STGW;                                                 \
    uint32_t* sBl = smw + 6 * STGW;                                                 \
    const int t = threadIdx.x;                                                      \
    const int wid = t >> 5, lane = t & 31;                                          \
    const int gr = lane >> 2, gc = lane & 3;                                        \
    const int wm = wid >> 2, wn = wid & 3;                                          \
    float acc[4][4][4];                                                             \
    _Pragma("unroll")                                                               \
    for (int a = 0; a < 4; a++)                                                     \
        _Pragma("unroll")                                                           \
        for (int bq = 0; bq < 4; bq++)                                              \
            _Pragma("unroll")                                                       \
            for (int k = 0; k < 4; k++) acc[a][bq][k] = 0.0f;                       \
    auto load_stage = [&](int ch, int st) {                                         \
        const int c0w = ch * 16;                                                    \
        _Pragma("unroll")                                                           \
        for (int j = 0; j < 2; j++) {                                               \
            const int idx = j * 256 + t;                                            \
            const int r = idx >> 2, w4 = (idx & 3) << 2;                            \
            const uint32_t soff = (st * STGW + r * STRD + w4) * 4;                  \
            CP_ASYNC16(sptr(sAh) + soff, AH + (size_t)(M0 + r) * 128 + c0w + w4);   \
            CP_ASYNC16(sptr(sAl) + soff, AL + (size_t)(M0 + r) * 128 + c0w + w4);   \
            CP_ASYNC16(sptr(sBh) + soff, BH + (size_t)(N0G + r) * 128 + c0w + w4);  \
            CP_ASYNC16(sptr(sBl) + soff, BL + (size_t)(N0G + r) * 128 + c0w + w4);  \
        }                                                                           \
    };                                                                              \
    load_stage(0, 0);                                                               \
    CP_COMMIT();                                                                    \
    CP_WAIT0();                                                                     \
    __syncthreads();                                                                \
    _Pragma("unroll 1")                                                             \
    for (int ch = 0; ch < 8; ch++) {                                                \
        const int cur = ch & 1;                                                     \
        if (ch < 7) { load_stage(ch + 1, 1 - cur); CP_COMMIT(); }                   \
        _Pragma("unroll")                                                           \
        for (int ks = 0; ks < 2; ks++) {                                            \
            uint32_t ah[4][4], al[4][4];                                            \
            _Pragma("unroll")                                                       \
            for (int mf = 0; mf < 4; mf++) {                                        \
                const int row = wm * 64 + mf * 16 + gr;                             \
                const int base = cur * STGW + row * STRD + ks * 8 + gc;             \
                ah[mf][0] = sAh[base];                                              \
                ah[mf][1] = sAh[base + 8 * STRD];                                   \
                ah[mf][2] = sAh[base + 4];                                          \
                ah[mf][3] = sAh[base + 8 * STRD + 4];                               \
                al[mf][0] = sAl[base];                                              \
                al[mf][1] = sAl[base + 8 * STRD];                                   \
                al[mf][2] = sAl[base + 4];                                          \
                al[mf][3] = sAl[base + 8 * STRD + 4];                               \
            }                                                                       \
            _Pragma("unroll")                                                       \
            for (int nf = 0; nf < 4; nf++) {                                        \
                const int rowb = wn * 32 + nf * 8 + gr;                             \
                const int bas = cur * STGW + rowb * STRD + ks * 8 + gc;             \
                const uint32_t bh0 = sBh[bas], bh1 = sBh[bas + 4];                  \
                const uint32_t bl0 = sBl[bas], bl1 = sBl[bas + 4];                  \
                _Pragma("unroll")                                                   \
                for (int mf = 0; mf < 4; mf++) {                                    \
                    mma16816(acc[mf][nf], ah[mf], bh0, bh1);                        \
                    mma16816(acc[mf][nf], al[mf], bh0, bh1);                        \
                    mma16816(acc[mf][nf], ah[mf], bl0, bl1);                        \
                }                                                                   \
            }                                                                       \
        }                                                                           \
        if (ch < 7) CP_WAIT0();                                                     \
        __syncthreads();                                                            \
    }

// =====================================================================
// Kernel: QKV GEMM (tensor cores) + layout epilogue via smem bounce.
//   Y[o][ng] = sum_c Wq[o][c] X[ng][c] + bias[o]
// =====================================================================
__global__ __launch_bounds__(256) void qkv_gemm_kernel(const float* __restrict__ bias)
{
    extern __shared__ uint32_t smw[];
    const int n0g = blockIdx.x * 128;
    const int o0  = blockIdx.y * 128;

    GEMM_MAINLOOP(g_WqPh, g_WqPl, g_XPh, g_XPl, o0, n0g)

    // bias add
    #pragma unroll
    for (int mf = 0; mf < 4; mf++) {
        const int o_r = o0 + wm * 64 + mf * 16 + gr;
        const float b0 = bias[o_r], b1 = bias[o_r + 8];
        #pragma unroll
        for (int nf = 0; nf < 4; nf++) {
            acc[mf][nf][0] += b0; acc[mf][nf][1] += b0;
            acc[mf][nf][2] += b1; acc[mf][nf][3] += b1;
        }
    }

    // bounce tile through smem as fp32 [128 o][128 n], stride 129
    float* sf = (float*)smw;
    __syncthreads();
    #pragma unroll
    for (int mf = 0; mf < 4; mf++) {
        const int o_l = wm * 64 + mf * 16 + gr;
        #pragma unroll
        for (int nf = 0; nf < 4; nf++) {
            const int n_l = wn * 32 + nf * 8 + 2 * gc;
            sf[o_l * 129 + n_l]           = acc[mf][nf][0];
            sf[o_l * 129 + n_l + 1]       = acc[mf][nf][1];
            sf[(o_l + 8) * 129 + n_l]     = acc[mf][nf][2];
            sf[(o_l + 8) * 129 + n_l + 1] = acc[mf][nf][3];
        }
    }
    __syncthreads();

    if (o0 < CC) {
        // Q region: fp32 [ng][c]
        #pragma unroll 4
        for (int idx = t; idx < 8192; idx += 256) {
            const int nl = idx >> 6, w = idx & 63;
            const int ol = 2 * w;
            const float f0 = sf[ol * 129 + nl], f1 = sf[(ol + 1) * 129 + nl];
            const size_t ng = n0g + nl;
            *(float2*)(g_Q + ng * CC + o0 + ol) = make_float2(f0, f1);
        }
    } else if (o0 < 2 * CC) {
        // K region: split pairs along d -> [bh][n][d/2]
        #pragma unroll 4
        for (int idx = t; idx < 8192; idx += 256) {
            const int nl = idx >> 6, w = idx & 63;
            const int ol = 2 * w;
            uint32_t hi, lo;
            split2(sf[ol * 129 + nl], sf[(ol + 1) * 129 + nl], hi, lo);
            const int ng = n0g + nl;
            const int b = (ng >= NN) ? 1 : 0;
            const int n = ng - b * NN;
            const int d = (o0 - CC) + ol;
            const size_t off = ((size_t)(b * NH + (d >> 5)) * NN + n) * (HD/2) + ((d & 31) >> 1);
            g_KPh[off] = hi;
            g_KPl[off] = lo;
        }
    } else {
        // V region: split pairs along n -> [bh][d][n/2]
        const int b = (n0g >= NN) ? 1 : 0;
        const int nb = n0g - b * NN;
        #pragma unroll 4
        for (int idx = t; idx < 8192; idx += 256) {
            const int ol = idx >> 6, w = idx & 63;
            uint32_t hi, lo;
            split2(sf[ol * 129 + 2 * w], sf[ol * 129 + 2 * w + 1], hi, lo);
            const int d = (o0 - 2 * CC) + ol;
            const size_t off = ((size_t)(b * NH + (d >> 5)) * HD + (d & 31)) * (NN/2) + (nb >> 1) + w;
            g_VPh[off] = hi;
            g_VPl[off] = lo;
        }
    }
}

// =====================================================================
// Kernel: proj GEMM (tensor cores) + bias + residual, direct epilogue.
//   out[b][c][n] = sum_c' Wp[c][c'] O[ng][c'] + bp[c] + x[b][c][n]
// =====================================================================
__global__ __launch_bounds__(256) void proj_gemm_kernel(
    const float* __restrict__ X, const float* __restrict__ bp,
    float* __restrict__ out)
{
    extern __shared__ uint32_t smw[];
    const int n0g = blockIdx.x * 128;
    const int c0  = blockIdx.y * 128;

    GEMM_MAINLOOP(g_WpPh, g_WpPl, g_OPh, g_OPl, c0, n0g)

    const int b = (n0g >= NN) ? 1 : 0;
    #pragma unroll
    for (int mf = 0; mf < 4; mf++) {
        const int c_r = c0 + wm * 64 + mf * 16 + gr;
        const float bi0 = bp[c_r], bi1 = bp[c_r + 8];
        #pragma unroll
        for (int nf = 0; nf < 4; nf++) {
            const int ngc = n0g + wn * 32 + nf * 8 + 2 * gc;
            const int n = ngc - b * NN;
            const size_t o0i = (size_t)b * CC * NN + (size_t)c_r * NN + n;
            const size_t o1i = o0i + 8 * NN;
            float2 x0 = *(const float2*)(X + o0i);
            float2 x1 = *(const float2*)(X + o1i);
            *(float2*)(out + o0i) = make_float2(acc[mf][nf][0] + bi0 + x0.x,
                                                acc[mf][nf][1] + bi0 + x0.y);
            *(float2*)(out + o1i) = make_float2(acc[mf][nf][2] + bi1 + x1.x,
                                                acc[mf][nf][3] + bi1 + x1.y);
        }
    }
}

// =====================================================================
// Kernel: flash attention (split-bf16 HMMA, as R3) — Q from g_Q, out split.
// =====================================================================
#define KS 2560   // 128 rows * 20
#define VS 2176   // 32 rows * 68

__global__ __launch_bounds__(256) void attn_kernel()
{
    extern __shared__ uint32_t sm[];
    uint32_t* sKh = sm;
    uint32_t* sKl = sm + 2 * KS;
    uint32_t* sVh = sm + 4 * KS;
    uint32_t* sVl = sm + 4 * KS + 2 * VS;

    const int bh = blockIdx.y;
    const int b  = bh >> 3, h = bh & 7;
    const int q0 = blockIdx.x * 128;
    const int t  = threadIdx.x;
    const int wid = t >> 5, lane = t & 31;
    const int gr = lane >> 2, gc = lane & 3;

    const uint32_t* gKh = g_KPh + (size_t)bh * NN * (HD/2);
    const uint32_t* gKl = g_KPl + (size_t)bh * NN * (HD/2);
    const uint32_t* gVh = g_VPh + (size_t)bh * HD * (NN/2);
    const uint32_t* gVl = g_VPl + (size_t)bh * HD * (NN/2);

    uint32_t aQh[2][4], aQl[2][4];
    {
        const float scale = 0.17677669529663689f;
        const float* Qb = g_Q + ((size_t)b * NN + q0 + wid * 16) * CC + h * HD;
        #pragma unroll
        for (int ks = 0; ks < 2; ks++) {
            #pragma unroll
            for (int p = 0; p < 4; p++) {
                const int row = gr + ((p & 1) ? 8 : 0);
                const int col = 2 * gc + ((p & 2) ? 8 : 0) + ks * 16;
                float2 q = *(const float2*)(Qb + (size_t)row * CC + col);
                q.x *= scale; q.y *= scale;
                split2(q.x, q.y, aQh[ks][p], aQl[ks][p]);
            }
        }
    }

    auto load_tile = [&](int k0, int s) {
        #pragma unroll
        for (int j = 0; j < 4; j++) {
            const int idx = j * 256 + t;
            const int arr = idx >> 9;
            const int rem = idx & 511;
            const int r = rem >> 2, chn = (rem & 3) << 2;
            const uint32_t* src = (arr ? gKl : gKh) + (size_t)(k0 + r) * (HD/2) + chn;
            CP_ASYNC16(sptr((arr ? sKl : sKh) + s * KS + r * 20 + chn), src);
        }
        #pragma unroll
        for (int j = 0; j < 4; j++) {
            const int idx = j * 256 + t;
            const int arr = idx >> 9;
            const int rem = idx & 511;
            const int r = rem >> 4, chn = (rem & 15) << 2;
            const uint32_t* src = (arr ? gVl : gVh) + (size_t)r * (NN/2) + (k0 >> 1) + chn;
            CP_ASYNC16(sptr((arr ? sVl : sVh) + s * VS + r * 68 + chn), src);
        }
    };

    float m_[2] = {-1e30f, -1e30f};
    float l_[2] = {0.0f, 0.0f};
    float o[4][4];
    #pragma unroll
    for (int nv = 0; nv < 4; nv++)
        #pragma unroll
        for (int k = 0; k < 4; k++) o[nv][k] = 0.0f;

    load_tile(0, 0);
    CP_COMMIT();
    CP_WAIT0();
    __syncthreads();

    #pragma unroll 1
    for (int kt = 0; kt < 18; kt++) {
        const int cur = kt & 1;
        if (kt < 17) { load_tile((kt + 1) * 128, 1 - cur); CP_COMMIT(); }

        float c[16][4];
        #pragma unroll
        for (int nf = 0; nf < 16; nf++)
            #pragma unroll
            for (int k = 0; k < 4; k++) c[nf][k] = 0.0f;

        const uint32_t* Kh = sKh + cur * KS;
        const uint32_t* Kl = sKl + cur * KS;
        #pragma unroll
        for (int nf = 0; nf < 16; nf++) {
            const int base = (nf * 8 + gr) * 20;
            #pragma unroll
            for (int ks = 0; ks < 2; ks++) {
                const uint32_t bh0 = Kh[base + ks * 8 + gc];
                const uint32_t bh1 = Kh[base + ks * 8 + 4 + gc];
                const uint32_t bl0 = Kl[base + ks * 8 + gc];
                const uint32_t bl1 = Kl[base + ks * 8 + 4 + gc];
                mma16816(c[nf], aQh[ks], bh0, bh1);
                mma16816(c[nf], aQl[ks], bh0, bh1);
                mma16816(c[nf], aQh[ks], bl0, bl1);
            }
        }

        float mx0 = -1e30f, mx1 = -1e30f;
        #pragma unroll
        for (int nf = 0; nf < 16; nf++) {
            mx0 = fmaxf(mx0, fmaxf(c[nf][0], c[nf][1]));
            mx1 = fmaxf(mx1, fmaxf(c[nf][2], c[nf][3]));
        }
        mx0 = fmaxf(mx0, __shfl_xor_sync(0xffffffffu, mx0, 1));
        mx0 = fmaxf(mx0, __shfl_xor_sync(0xffffffffu, mx0, 2));
        mx1 = fmaxf(mx1, __shfl_xor_sync(0xffffffffu, mx1, 1));
        mx1 = fmaxf(mx1, __shfl_xor_sync(0xffffffffu, mx1, 2));
        const float mn0 = fmaxf(m_[0], mx0);
        const float mn1 = fmaxf(m_[1], mx1);
        const float al0 = __expf(m_[0] - mn0);
        const float al1 = __expf(m_[1] - mn1);
        m_[0] = mn0; m_[1] = mn1;

        float s0 = 0.0f, s1 = 0.0f;
        #pragma unroll
        for (int nf = 0; nf < 16; nf++) {
            c[nf][0] = __expf(c[nf][0] - mn0);
            c[nf][1] = __expf(c[nf][1] - mn0);
            c[nf][2] = __expf(c[nf][2] - mn1);
            c[nf][3] = __expf(c[nf][3] - mn1);
            s0 += c[nf][0] + c[nf][1];
            s1 += c[nf][2] + c[nf][3];
        }
        s0 += __shfl_xor_sync(0xffffffffu, s0, 1);
        s0 += __shfl_xor_sync(0xffffffffu, s0, 2);
        s1 += __shfl_xor_sync(0xffffffffu, s1, 1);
        s1 += __shfl_xor_sync(0xffffffffu, s1, 2);
        l_[0] = l_[0] * al0 + s0;
        l_[1] = l_[1] * al1 + s1;

        #pragma unroll
        for (int nv = 0; nv < 4; nv++) {
            o[nv][0] *= al0; o[nv][1] *= al0;
            o[nv][2] *= al1; o[nv][3] *= al1;
        }

        const uint32_t* Vh = sVh + cur * VS;
        const uint32_t* Vl = sVl + cur * VS;
        #pragma unroll
        for (int j = 0; j < 8; j++) {
            uint32_t pAh[4], pAl[4];
            split2(c[2*j][0],   c[2*j][1],   pAh[0], pAl[0]);
            split2(c[2*j][2],   c[2*j][3],   pAh[1], pAl[1]);
            split2(c[2*j+1][0], c[2*j+1][1], pAh[2], pAl[2]);
            split2(c[2*j+1][2], c[2*j+1][3], pAh[3], pAl[3]);
            #pragma unroll
            for (int nv = 0; nv < 4; nv++) {
                const int vb = (nv * 8 + gr) * 68 + j * 8;
                const uint32_t vh0 = Vh[vb + gc], vh1 = Vh[vb + 4 + gc];
                const uint32_t vl0 = Vl[vb + gc], vl1 = Vl[vb + 4 + gc];
                mma16816(o[nv], pAh, vh0, vh1);
                mma16816(o[nv], pAl, vh0, vh1);
                mma16816(o[nv], pAh, vl0, vl1);
            }
        }

        CP_WAIT0();
        __syncthreads();
    }

    // finalize: normalize + split-pack to g_OP [ng][c/2]
    const float inv0 = 1.0f / l_[0];
    const float inv1 = 1.0f / l_[1];
    const size_t ng0 = (size_t)b * NN + q0 + wid * 16 + gr;
    const size_t ng1 = ng0 + 8;
    #pragma unroll
    for (int nv = 0; nv < 4; nv++) {
        const int wrd = h * 16 + nv * 4 + gc;
        uint32_t hi, lo;
        split2(o[nv][0] * inv0, o[nv][1] * inv0, hi, lo);
        g_OPh[ng0 * 128 + wrd] = hi;
        g_OPl[ng0 * 128 + wrd] = lo;
        split2(o[nv][2] * inv1, o[nv][3] * inv1, hi, lo);
        g_OPh[ng1 * 128 + wrd] = hi;
        g_OPl[ng1 * 128 + wrd] = lo;
    }
}

// =====================================================================
extern "C" void kernel_launch(void* const* d_in, const int* in_sizes, int n_in,
                              void* d_out, int out_size)
{
    const float* x      = (const float*)d_in[0];
    const float* w_qkv  = (const float*)d_in[1];
    const float* b_qkv  = (const float*)d_in[2];
    const float* w_proj = (const float*)d_in[3];
    const float* b_proj = (const float*)d_in[4];
    float* out = (float*)d_out;

    static bool attr_done = false;
    const int gemm_smem = 8 * STGW * 4;              // 81920 B
    const int attn_smem = (4 * KS + 4 * VS) * 4;     // 75776 B
    if (!attr_done) {
        cudaFuncSetAttribute(qkv_gemm_kernel, cudaFuncAttributeMaxDynamicSharedMemorySize, gemm_smem);
        cudaFuncSetAttribute(proj_gemm_kernel, cudaFuncAttributeMaxDynamicSharedMemorySize, gemm_smem);
        cudaFuncSetAttribute(attn_kernel, cudaFuncAttributeMaxDynamicSharedMemorySize, attn_smem);
        attr_done = true;
    }

    split_w_kernel<<<(OC3 + CC) * 128 / 256, 256>>>(w_qkv, w_proj);
    split_x_kernel<<<dim3(NN / 64, CC / 64, BB), 256>>>(x);
    qkv_gemm_kernel<<<dim3(NG / 128, OC3 / 128), 256, gemm_smem>>>(b_qkv);
    attn_kernel<<<dim3(NN / 128, NBH), 256, attn_smem>>>();
    proj_gemm_kernel<<<dim3(NG / 128, CC / 128), 256, gemm_smem>>>(x, b_proj, out);
}

// round 5
// speedup vs baseline: 2.9086x; 1.1734x over previous
#include <cuda_runtime.h>
#include <cuda_bf16.h>
#include <cstdint>

#define BB   2
#define CC   256
#define NN   2304
#define OC3  768
#define NH   8
#define HD   32
#define NBH  (BB*NH)
#define NG   (BB*NN)     // 4608 flattened (b,n)

// ---------------- device scratch ----------------
__device__ float g_Q[NG * CC];                               // Q fp32 [ng][c]
__device__ __align__(16) uint32_t g_XPh[NG * 128];           // X split pairs along c [ng][c/2]
__device__ __align__(16) uint32_t g_XPl[NG * 128];
__device__ __align__(16) uint32_t g_WqPh[OC3 * 128];         // W_qkv split [o][c/2]
__device__ __align__(16) uint32_t g_WqPl[OC3 * 128];
__device__ __align__(16) uint32_t g_WpPh[CC * 128];          // W_proj split [c][c'/2]
__device__ __align__(16) uint32_t g_WpPl[CC * 128];
__device__ __align__(16) uint32_t g_KPh[NBH * NN * (HD/2)];  // K pairs along d [bh][n][d/2]
__device__ __align__(16) uint32_t g_KPl[NBH * NN * (HD/2)];
__device__ __align__(16) uint32_t g_VPh[NBH * HD * (NN/2)];  // V^T pairs along n [bh][d][n/2]
__device__ __align__(16) uint32_t g_VPl[NBH * HD * (NN/2)];
__device__ __align__(16) uint32_t g_OPh[NG * 128];           // attn out split [ng][c/2]
__device__ __align__(16) uint32_t g_OPl[NG * 128];

// ---------------- helpers ----------------
__device__ __forceinline__ uint32_t bf2_pack(float lo_elem, float hi_elem) {
    uint32_t d;
    asm("cvt.rn.bf16x2.f32 %0, %1, %2;" : "=r"(d) : "f"(hi_elem), "f"(lo_elem));
    return d;
}
__device__ __forceinline__ float2 bf2_unpack(uint32_t v) {
    __nv_bfloat162 h;
    *reinterpret_cast<uint32_t*>(&h) = v;
    return __bfloat1622float2(h);
}
__device__ __forceinline__ void split2(float x, float y, uint32_t& hi, uint32_t& lo) {
    hi = bf2_pack(x, y);
    float2 f = bf2_unpack(hi);
    lo = bf2_pack(x - f.x, y - f.y);
}
__device__ __forceinline__ void mma16816(float c[4], const uint32_t a[4], uint32_t b0, uint32_t b1) {
    asm volatile(
        "mma.sync.aligned.m16n8k16.row.col.f32.bf16.bf16.f32 "
        "{%0,%1,%2,%3}, {%4,%5,%6,%7}, {%8,%9}, {%0,%1,%2,%3};"
        : "+f"(c[0]), "+f"(c[1]), "+f"(c[2]), "+f"(c[3])
        : "r"(a[0]), "r"(a[1]), "r"(a[2]), "r"(a[3]), "r"(b0), "r"(b1));
}
#define CP_ASYNC16(dst, src) \
    asm volatile("cp.async.cg.shared.global [%0], [%1], 16;" :: "r"(dst), "l"(src))
#define CP_COMMIT() asm volatile("cp.async.commit_group;")
#define CP_WAIT0()  asm volatile("cp.async.wait_group 0;" ::: "memory")
__device__ __forceinline__ uint32_t sptr(const void* p) {
    return (uint32_t)__cvta_generic_to_shared(p);
}

// =====================================================================
// Prep A: split weights into bf16x2 hi/lo words (pairs along input chan).
// =====================================================================
__global__ __launch_bounds__(256) void split_w_kernel(
    const float* __restrict__ Wq, const float* __restrict__ Wp)
{
    const int idx = blockIdx.x * 256 + threadIdx.x;  // 131072 total
    const int r = idx >> 7, w = idx & 127;
    if (r < OC3) {
        float2 f = *(const float2*)(Wq + (size_t)r * CC + 2 * w);
        uint32_t hi, lo;
        split2(f.x, f.y, hi, lo);
        g_WqPh[r * 128 + w] = hi;
        g_WqPl[r * 128 + w] = lo;
    } else {
        const int rr = r - OC3;
        float2 f = *(const float2*)(Wp + (size_t)rr * CC + 2 * w);
        uint32_t hi, lo;
        split2(f.x, f.y, hi, lo);
        g_WpPh[rr * 128 + w] = hi;
        g_WpPl[rr * 128 + w] = lo;
    }
}

// =====================================================================
// Prep B: transpose-split X [b][c][n] -> pairs along c, [ng][c/2].
// =====================================================================
__global__ __launch_bounds__(256) void split_x_kernel(const float* __restrict__ X)
{
    __shared__ float s[64][65];
    const int b  = blockIdx.z;
    const int c0 = blockIdx.y * 64;
    const int n0 = blockIdx.x * 64;
    const int t  = threadIdx.x;

    #pragma unroll
    for (int j = 0; j < 16; j++) {
        const int idx = j * 256 + t;
        const int r = idx >> 6, col = idx & 63;
        s[r][col] = X[(size_t)b * CC * NN + (size_t)(c0 + r) * NN + n0 + col];
    }
    __syncthreads();
    #pragma unroll
    for (int j = 0; j < 8; j++) {
        const int idx = j * 256 + t;
        const int nl = idx >> 5, w = idx & 31;
        uint32_t hi, lo;
        split2(s[2 * w][nl], s[2 * w + 1][nl], hi, lo);
        const size_t o = ((size_t)b * NN + n0 + nl) * 128 + (c0 >> 1) + w;
        g_XPh[o] = hi;
        g_XPl[o] = lo;
    }
}

// =====================================================================
// Shared GEMM mainloop (128M x 128N CTA, K=256, chunk 32).
// =====================================================================
#define STRD 20
#define STGW (128 * STRD)

#define GEMM_MAINLOOP(AH, AL, BH, BL, M0, N0G)                                      \
    uint32_t* sAh = smw;                                                            \
    uint32_t* sAl = smw + 2 * STGW;                                                 \
    uint32_t* sBh = smw + 4 * STGW;                                                 \
    uint32_t* sBl = smw + 6 * STGW;                                                 \
    const int t = threadIdx.x;                                                      \
    const int wid = t >> 5, lane = t & 31;                                          \
    const int gr = lane >> 2, gc = lane & 3;                                        \
    const int wm = wid >> 2, wn = wid & 3;                                          \
    float acc[4][4][4];                                                             \
    _Pragma("unroll")                                                               \
    for (int a = 0; a < 4; a++)                                                     \
        _Pragma("unroll")                                                           \
        for (int bq = 0; bq < 4; bq++)                                              \
            _Pragma("unroll")                                                       \
            for (int k = 0; k < 4; k++) acc[a][bq][k] = 0.0f;                       \
    auto load_stage = [&](int ch, int st) {                                         \
        const int c0w = ch * 16;                                                    \
        _Pragma("unroll")                                                           \
        for (int j = 0; j < 2; j++) {                                               \
            const int idx = j * 256 + t;                                            \
            const int r = idx >> 2, w4 = (idx & 3) << 2;                            \
            const uint32_t soff = (st * STGW + r * STRD + w4) * 4;                  \
            CP_ASYNC16(sptr(sAh) + soff, AH + (size_t)(M0 + r) * 128 + c0w + w4);   \
            CP_ASYNC16(sptr(sAl) + soff, AL + (size_t)(M0 + r) * 128 + c0w + w4);   \
            CP_ASYNC16(sptr(sBh) + soff, BH + (size_t)(N0G + r) * 128 + c0w + w4);  \
            CP_ASYNC16(sptr(sBl) + soff, BL + (size_t)(N0G + r) * 128 + c0w + w4);  \
        }                                                                           \
    };                                                                              \
    load_stage(0, 0);                                                               \
    CP_COMMIT();                                                                    \
    CP_WAIT0();                                                                     \
    __syncthreads();                                                                \
    _Pragma("unroll 1")                                                             \
    for (int ch = 0; ch < 8; ch++) {                                                \
        const int cur = ch & 1;                                                     \
        if (ch < 7) { load_stage(ch + 1, 1 - cur); CP_COMMIT(); }                   \
        _Pragma("unroll")                                                           \
        for (int ks = 0; ks < 2; ks++) {                                            \
            uint32_t ah[4][4], al[4][4];                                            \
            _Pragma("unroll")                                                       \
            for (int mf = 0; mf < 4; mf++) {                                        \
                const int row = wm * 64 + mf * 16 + gr;                             \
                const int base = cur * STGW + row * STRD + ks * 8 + gc;             \
                ah[mf][0] = sAh[base];                                              \
                ah[mf][1] = sAh[base + 8 * STRD];                                   \
                ah[mf][2] = sAh[base + 4];                                          \
                ah[mf][3] = sAh[base + 8 * STRD + 4];                               \
                al[mf][0] = sAl[base];                                              \
                al[mf][1] = sAl[base + 8 * STRD];                                   \
                al[mf][2] = sAl[base + 4];                                          \
                al[mf][3] = sAl[base + 8 * STRD + 4];                               \
            }                                                                       \
            _Pragma("unroll")                                                       \
            for (int nf = 0; nf < 4; nf++) {                                        \
                const int rowb = wn * 32 + nf * 8 + gr;                             \
                const int bas = cur * STGW + rowb * STRD + ks * 8 + gc;             \
                const uint32_t bh0 = sBh[bas], bh1 = sBh[bas + 4];                  \
                const uint32_t bl0 = sBl[bas], bl1 = sBl[bas + 4];                  \
                _Pragma("unroll")                                                   \
                for (int mf = 0; mf < 4; mf++) {                                    \
                    mma16816(acc[mf][nf], ah[mf], bh0, bh1);                        \
                    mma16816(acc[mf][nf], al[mf], bh0, bh1);                        \
                    mma16816(acc[mf][nf], ah[mf], bl0, bl1);                        \
                }                                                                   \
            }                                                                       \
        }                                                                           \
        if (ch < 7) CP_WAIT0();                                                     \
        __syncthreads();                                                            \
    }

// =====================================================================
// QKV GEMM + layout epilogue via smem bounce.
// =====================================================================
__global__ __launch_bounds__(256) void qkv_gemm_kernel(const float* __restrict__ bias)
{
    extern __shared__ uint32_t smw[];
    const int n0g = blockIdx.x * 128;
    const int o0  = blockIdx.y * 128;

    GEMM_MAINLOOP(g_WqPh, g_WqPl, g_XPh, g_XPl, o0, n0g)

    #pragma unroll
    for (int mf = 0; mf < 4; mf++) {
        const int o_r = o0 + wm * 64 + mf * 16 + gr;
        const float b0 = bias[o_r], b1 = bias[o_r + 8];
        #pragma unroll
        for (int nf = 0; nf < 4; nf++) {
            acc[mf][nf][0] += b0; acc[mf][nf][1] += b0;
            acc[mf][nf][2] += b1; acc[mf][nf][3] += b1;
        }
    }

    float* sf = (float*)smw;
    __syncthreads();
    #pragma unroll
    for (int mf = 0; mf < 4; mf++) {
        const int o_l = wm * 64 + mf * 16 + gr;
        #pragma unroll
        for (int nf = 0; nf < 4; nf++) {
            const int n_l = wn * 32 + nf * 8 + 2 * gc;
            sf[o_l * 129 + n_l]           = acc[mf][nf][0];
            sf[o_l * 129 + n_l + 1]       = acc[mf][nf][1];
            sf[(o_l + 8) * 129 + n_l]     = acc[mf][nf][2];
            sf[(o_l + 8) * 129 + n_l + 1] = acc[mf][nf][3];
        }
    }
    __syncthreads();

    if (o0 < CC) {
        #pragma unroll 4
        for (int idx = t; idx < 8192; idx += 256) {
            const int nl = idx >> 6, w = idx & 63;
            const int ol = 2 * w;
            const float f0 = sf[ol * 129 + nl], f1 = sf[(ol + 1) * 129 + nl];
            const size_t ng = n0g + nl;
            *(float2*)(g_Q + ng * CC + o0 + ol) = make_float2(f0, f1);
        }
    } else if (o0 < 2 * CC) {
        #pragma unroll 4
        for (int idx = t; idx < 8192; idx += 256) {
            const int nl = idx >> 6, w = idx & 63;
            const int ol = 2 * w;
            uint32_t hi, lo;
            split2(sf[ol * 129 + nl], sf[(ol + 1) * 129 + nl], hi, lo);
            const int ng = n0g + nl;
            const int b = (ng >= NN) ? 1 : 0;
            const int n = ng - b * NN;
            const int d = (o0 - CC) + ol;
            const size_t off = ((size_t)(b * NH + (d >> 5)) * NN + n) * (HD/2) + ((d & 31) >> 1);
            g_KPh[off] = hi;
            g_KPl[off] = lo;
        }
    } else {
        const int b = (n0g >= NN) ? 1 : 0;
        const int nb = n0g - b * NN;
        #pragma unroll 4
        for (int idx = t; idx < 8192; idx += 256) {
            const int ol = idx >> 6, w = idx & 63;
            uint32_t hi, lo;
            split2(sf[ol * 129 + 2 * w], sf[ol * 129 + 2 * w + 1], hi, lo);
            const int d = (o0 - 2 * CC) + ol;
            const size_t off = ((size_t)(b * NH + (d >> 5)) * HD + (d & 31)) * (NN/2) + (nb >> 1) + w;
            g_VPh[off] = hi;
            g_VPl[off] = lo;
        }
    }
}

// =====================================================================
// proj GEMM + bias + residual, direct epilogue.
// =====================================================================
__global__ __launch_bounds__(256) void proj_gemm_kernel(
    const float* __restrict__ X, const float* __restrict__ bp,
    float* __restrict__ out)
{
    extern __shared__ uint32_t smw[];
    const int n0g = blockIdx.x * 128;
    const int c0  = blockIdx.y * 128;

    GEMM_MAINLOOP(g_WpPh, g_WpPl, g_OPh, g_OPl, c0, n0g)

    const int b = (n0g >= NN) ? 1 : 0;
    #pragma unroll
    for (int mf = 0; mf < 4; mf++) {
        const int c_r = c0 + wm * 64 + mf * 16 + gr;
        const float bi0 = bp[c_r], bi1 = bp[c_r + 8];
        #pragma unroll
        for (int nf = 0; nf < 4; nf++) {
            const int ngc = n0g + wn * 32 + nf * 8 + 2 * gc;
            const int n = ngc - b * NN;
            const size_t o0i = (size_t)b * CC * NN + (size_t)c_r * NN + n;
            const size_t o1i = o0i + 8 * NN;
            float2 x0 = *(const float2*)(X + o0i);
            float2 x1 = *(const float2*)(X + o1i);
            *(float2*)(out + o0i) = make_float2(acc[mf][nf][0] + bi0 + x0.x,
                                                acc[mf][nf][1] + bi0 + x0.y);
            *(float2*)(out + o1i) = make_float2(acc[mf][nf][2] + bi1 + x1.x,
                                                acc[mf][nf][3] + bi1 + x1.y);
        }
    }
}

// =====================================================================
// Flash attention: k-tile 64 (low regs -> 2 CTAs/SM), 128 q rows/CTA.
// smem/CTA: (4*1280 + 4*1152)*4 = 38912 B.
// =====================================================================
#define KS 1280   // 64 rows * 20 (16 data + 4 pad)
#define VS 1152   // 32 rows * 36 (32 data + 4 pad)

__global__ __launch_bounds__(256, 2) void attn_kernel()
{
    extern __shared__ uint32_t sm[];
    uint32_t* sKh = sm;
    uint32_t* sKl = sm + 2 * KS;
    uint32_t* sVh = sm + 4 * KS;
    uint32_t* sVl = sm + 4 * KS + 2 * VS;

    const int bh = blockIdx.y;
    const int b  = bh >> 3, h = bh & 7;
    const int q0 = blockIdx.x * 128;
    const int t  = threadIdx.x;
    const int wid = t >> 5, lane = t & 31;
    const int gr = lane >> 2, gc = lane & 3;

    const uint32_t* gKh = g_KPh + (size_t)bh * NN * (HD/2);
    const uint32_t* gKl = g_KPl + (size_t)bh * NN * (HD/2);
    const uint32_t* gVh = g_VPh + (size_t)bh * HD * (NN/2);
    const uint32_t* gVl = g_VPl + (size_t)bh * HD * (NN/2);

    uint32_t aQh[2][4], aQl[2][4];
    {
        const float scale = 0.17677669529663689f;  // 1/sqrt(32)
        const float* Qb = g_Q + ((size_t)b * NN + q0 + wid * 16) * CC + h * HD;
        #pragma unroll
        for (int ks = 0; ks < 2; ks++) {
            #pragma unroll
            for (int p = 0; p < 4; p++) {
                const int row = gr + ((p & 1) ? 8 : 0);
                const int col = 2 * gc + ((p & 2) ? 8 : 0) + ks * 16;
                float2 q = *(const float2*)(Qb + (size_t)row * CC + col);
                q.x *= scale; q.y *= scale;
                split2(q.x, q.y, aQh[ks][p], aQl[ks][p]);
            }
        }
    }

    // 4 chunks of 16B per thread per stage (K 512 + V 512 chunks)
    auto load_tile = [&](int k0, int s) {
        #pragma unroll
        for (int j = 0; j < 2; j++) {
            const int idx = j * 256 + t;
            const int arr = idx >> 8;
            const int rem = idx & 255;
            const int r = rem >> 2, chn = (rem & 3) << 2;
            const uint32_t* src = (arr ? gKl : gKh) + (size_t)(k0 + r) * (HD/2) + chn;
            CP_ASYNC16(sptr((arr ? sKl : sKh) + s * KS + r * 20 + chn), src);
        }
        #pragma unroll
        for (int j = 0; j < 2; j++) {
            const int idx = j * 256 + t;
            const int arr = idx >> 8;
            const int rem = idx & 255;
            const int r = rem >> 3, chn = (rem & 7) << 2;
            const uint32_t* src = (arr ? gVl : gVh) + (size_t)r * (NN/2) + (k0 >> 1) + chn;
            CP_ASYNC16(sptr((arr ? sVl : sVh) + s * VS + r * 36 + chn), src);
        }
    };

    float m_[2] = {-1e30f, -1e30f};
    float l_[2] = {0.0f, 0.0f};
    float o[4][4];
    #pragma unroll
    for (int nv = 0; nv < 4; nv++)
        #pragma unroll
        for (int k = 0; k < 4; k++) o[nv][k] = 0.0f;

    load_tile(0, 0);
    CP_COMMIT();
    CP_WAIT0();
    __syncthreads();

    #pragma unroll 1
    for (int kt = 0; kt < 36; kt++) {
        const int cur = kt & 1;
        if (kt < 35) { load_tile((kt + 1) * 64, 1 - cur); CP_COMMIT(); }

        // ---- S = Q K^T (3-product split) ----
        float c[8][4];
        #pragma unroll
        for (int nf = 0; nf < 8; nf++)
            #pragma unroll
            for (int k = 0; k < 4; k++) c[nf][k] = 0.0f;

        const uint32_t* Kh = sKh + cur * KS;
        const uint32_t* Kl = sKl + cur * KS;
        #pragma unroll
        for (int nf = 0; nf < 8; nf++) {
            const int base = (nf * 8 + gr) * 20;
            #pragma unroll
            for (int ks = 0; ks < 2; ks++) {
                const uint32_t bh0 = Kh[base + ks * 8 + gc];
                const uint32_t bh1 = Kh[base + ks * 8 + 4 + gc];
                const uint32_t bl0 = Kl[base + ks * 8 + gc];
                const uint32_t bl1 = Kl[base + ks * 8 + 4 + gc];
                mma16816(c[nf], aQh[ks], bh0, bh1);
                mma16816(c[nf], aQl[ks], bh0, bh1);
                mma16816(c[nf], aQh[ks], bl0, bl1);
            }
        }

        // ---- online softmax ----
        float mx0 = -1e30f, mx1 = -1e30f;
        #pragma unroll
        for (int nf = 0; nf < 8; nf++) {
            mx0 = fmaxf(mx0, fmaxf(c[nf][0], c[nf][1]));
            mx1 = fmaxf(mx1, fmaxf(c[nf][2], c[nf][3]));
        }
        mx0 = fmaxf(mx0, __shfl_xor_sync(0xffffffffu, mx0, 1));
        mx0 = fmaxf(mx0, __shfl_xor_sync(0xffffffffu, mx0, 2));
        mx1 = fmaxf(mx1, __shfl_xor_sync(0xffffffffu, mx1, 1));
        mx1 = fmaxf(mx1, __shfl_xor_sync(0xffffffffu, mx1, 2));
        const float mn0 = fmaxf(m_[0], mx0);
        const float mn1 = fmaxf(m_[1], mx1);
        const float al0 = __expf(m_[0] - mn0);
        const float al1 = __expf(m_[1] - mn1);
        m_[0] = mn0; m_[1] = mn1;

        float s0 = 0.0f, s1 = 0.0f;
        #pragma unroll
        for (int nf = 0; nf < 8; nf++) {
            c[nf][0] = __expf(c[nf][0] - mn0);
            c[nf][1] = __expf(c[nf][1] - mn0);
            c[nf][2] = __expf(c[nf][2] - mn1);
            c[nf][3] = __expf(c[nf][3] - mn1);
            s0 += c[nf][0] + c[nf][1];
            s1 += c[nf][2] + c[nf][3];
        }
        s0 += __shfl_xor_sync(0xffffffffu, s0, 1);
        s0 += __shfl_xor_sync(0xffffffffu, s0, 2);
        s1 += __shfl_xor_sync(0xffffffffu, s1, 1);
        s1 += __shfl_xor_sync(0xffffffffu, s1, 2);
        l_[0] = l_[0] * al0 + s0;
        l_[1] = l_[1] * al1 + s1;

        #pragma unroll
        for (int nv = 0; nv < 4; nv++) {
            o[nv][0] *= al0; o[nv][1] *= al0;
            o[nv][2] *= al1; o[nv][3] *= al1;
        }

        // ---- O += P V (3-product split) ----
        const uint32_t* Vh = sVh + cur * VS;
        const uint32_t* Vl = sVl + cur * VS;
        #pragma unroll
        for (int j = 0; j < 4; j++) {
            uint32_t pAh[4], pAl[4];
            split2(c[2*j][0],   c[2*j][1],   pAh[0], pAl[0]);
            split2(c[2*j][2],   c[2*j][3],   pAh[1], pAl[1]);
            split2(c[2*j+1][0], c[2*j+1][1], pAh[2], pAl[2]);
            split2(c[2*j+1][2], c[2*j+1][3], pAh[3], pAl[3]);
            #pragma unroll
            for (int nv = 0; nv < 4; nv++) {
                const int vb = (nv * 8 + gr) * 36 + j * 8;
                const uint32_t vh0 = Vh[vb + gc], vh1 = Vh[vb + 4 + gc];
                const uint32_t vl0 = Vl[vb + gc], vl1 = Vl[vb + 4 + gc];
                mma16816(o[nv], pAh, vh0, vh1);
                mma16816(o[nv], pAl, vh0, vh1);
                mma16816(o[nv], pAh, vl0, vl1);
            }
        }

        CP_WAIT0();
        __syncthreads();
    }

    // finalize: normalize + split-pack to g_OP [ng][c/2]
    const float inv0 = 1.0f / l_[0];
    const float inv1 = 1.0f / l_[1];
    const size_t ng0 = (size_t)b * NN + q0 + wid * 16 + gr;
    const size_t ng1 = ng0 + 8;
    #pragma unroll
    for (int nv = 0; nv < 4; nv++) {
        const int wrd = h * 16 + nv * 4 + gc;
        uint32_t hi, lo;
        split2(o[nv][0] * inv0, o[nv][1] * inv0, hi, lo);
        g_OPh[ng0 * 128 + wrd] = hi;
        g_OPl[ng0 * 128 + wrd] = lo;
        split2(o[nv][2] * inv1, o[nv][3] * inv1, hi, lo);
        g_OPh[ng1 * 128 + wrd] = hi;
        g_OPl[ng1 * 128 + wrd] = lo;
    }
}

// =====================================================================
extern "C" void kernel_launch(void* const* d_in, const int* in_sizes, int n_in,
                              void* d_out, int out_size)
{
    const float* x      = (const float*)d_in[0];
    const float* w_qkv  = (const float*)d_in[1];
    const float* b_qkv  = (const float*)d_in[2];
    const float* w_proj = (const float*)d_in[3];
    const float* b_proj = (const float*)d_in[4];
    float* out = (float*)d_out;

    static bool attr_done = false;
    const int gemm_smem = 8 * STGW * 4;              // 81920 B
    const int attn_smem = (4 * KS + 4 * VS) * 4;     // 38912 B
    if (!attr_done) {
        cudaFuncSetAttribute(qkv_gemm_kernel, cudaFuncAttributeMaxDynamicSharedMemorySize, gemm_smem);
        cudaFuncSetAttribute(proj_gemm_kernel, cudaFuncAttributeMaxDynamicSharedMemorySize, gemm_smem);
        cudaFuncSetAttribute(attn_kernel, cudaFuncAttributeMaxDynamicSharedMemorySize, attn_smem);
        attr_done = true;
    }

    split_w_kernel<<<(OC3 + CC) * 128 / 256, 256>>>(w_qkv, w_proj);
    split_x_kernel<<<dim3(NN / 64, CC / 64, BB), 256>>>(x);
    qkv_gemm_kernel<<<dim3(NG / 128, OC3 / 128), 256, gemm_smem>>>(b_qkv);
    attn_kernel<<<dim3(NN / 128, NBH), 256, attn_smem>>>();
    proj_gemm_kernel<<<dim3(NG / 128, CC / 128), 256, gemm_smem>>>(x, b_proj, out);
}

// round 6
// speedup vs baseline: 2.9865x; 1.0268x over previous
#include <cuda_runtime.h>
#include <cuda_bf16.h>
#include <cstdint>

#define BB   2
#define CC   256
#define NN   2304
#define OC3  768
#define NH   8
#define HD   32
#define NBH  (BB*NH)
#define NG   (BB*NN)     // 4608 flattened (b,n)

// ---------------- device scratch ----------------
__device__ float g_Q[NG * CC];                               // Q fp32 [ng][c]
__device__ __align__(16) uint32_t g_XPh[NG * 128];           // X split pairs along c [ng][c/2]
__device__ __align__(16) uint32_t g_XPl[NG * 128];
__device__ __align__(16) uint32_t g_WqPh[OC3 * 128];         // W_qkv split [o][c/2]
__device__ __align__(16) uint32_t g_WqPl[OC3 * 128];
__device__ __align__(16) uint32_t g_WpPh[CC * 128];          // W_proj split [c][c'/2]
__device__ __align__(16) uint32_t g_WpPl[CC * 128];
__device__ __align__(16) uint32_t g_KPh[NBH * NN * (HD/2)];  // K pairs along d [bh][n][d/2]
__device__ __align__(16) uint32_t g_KPl[NBH * NN * (HD/2)];
__device__ __align__(16) uint32_t g_VPh[NBH * HD * (NN/2)];  // V^T pairs along n [bh][d][n/2]
__device__ __align__(16) uint32_t g_VPl[NBH * HD * (NN/2)];
__device__ __align__(16) uint32_t g_OPh[NG * 128];           // attn out split [ng][c/2]
__device__ __align__(16) uint32_t g_OPl[NG * 128];

// ---------------- helpers ----------------
__device__ __forceinline__ uint32_t bf2_pack(float lo_elem, float hi_elem) {
    uint32_t d;
    asm("cvt.rn.bf16x2.f32 %0, %1, %2;" : "=r"(d) : "f"(hi_elem), "f"(lo_elem));
    return d;
}
__device__ __forceinline__ float2 bf2_unpack(uint32_t v) {
    __nv_bfloat162 h;
    *reinterpret_cast<uint32_t*>(&h) = v;
    return __bfloat1622float2(h);
}
__device__ __forceinline__ void split2(float x, float y, uint32_t& hi, uint32_t& lo) {
    hi = bf2_pack(x, y);
    float2 f = bf2_unpack(hi);
    lo = bf2_pack(x - f.x, y - f.y);
}
__device__ __forceinline__ void mma16816(float c[4], const uint32_t a[4], uint32_t b0, uint32_t b1) {
    asm volatile(
        "mma.sync.aligned.m16n8k16.row.col.f32.bf16.bf16.f32 "
        "{%0,%1,%2,%3}, {%4,%5,%6,%7}, {%8,%9}, {%0,%1,%2,%3};"
        : "+f"(c[0]), "+f"(c[1]), "+f"(c[2]), "+f"(c[3])
        : "r"(a[0]), "r"(a[1]), "r"(a[2]), "r"(a[3]), "r"(b0), "r"(b1));
}
__device__ __forceinline__ float ex2(float x) {
    float r;
    asm("ex2.approx.f32 %0, %1;" : "=f"(r) : "f"(x));
    return r;
}
#define CP_ASYNC16(dst, src) \
    asm volatile("cp.async.cg.shared.global [%0], [%1], 16;" :: "r"(dst), "l"(src))
#define CP_COMMIT() asm volatile("cp.async.commit_group;")
#define CP_WAIT0()  asm volatile("cp.async.wait_group 0;" ::: "memory")
__device__ __forceinline__ uint32_t sptr(const void* p) {
    return (uint32_t)__cvta_generic_to_shared(p);
}

// =====================================================================
// Prep A: split weights into bf16x2 hi/lo words (pairs along input chan).
// =====================================================================
__global__ __launch_bounds__(256) void split_w_kernel(
    const float* __restrict__ Wq, const float* __restrict__ Wp)
{
    const int idx = blockIdx.x * 256 + threadIdx.x;  // 131072 total
    const int r = idx >> 7, w = idx & 127;
    if (r < OC3) {
        float2 f = *(const float2*)(Wq + (size_t)r * CC + 2 * w);
        uint32_t hi, lo;
        split2(f.x, f.y, hi, lo);
        g_WqPh[r * 128 + w] = hi;
        g_WqPl[r * 128 + w] = lo;
    } else {
        const int rr = r - OC3;
        float2 f = *(const float2*)(Wp + (size_t)rr * CC + 2 * w);
        uint32_t hi, lo;
        split2(f.x, f.y, hi, lo);
        g_WpPh[rr * 128 + w] = hi;
        g_WpPl[rr * 128 + w] = lo;
    }
}

// =====================================================================
// Prep B: transpose-split X [b][c][n] -> pairs along c, [ng][c/2].
// =====================================================================
__global__ __launch_bounds__(256) void split_x_kernel(const float* __restrict__ X)
{
    __shared__ float s[64][65];
    const int b  = blockIdx.z;
    const int c0 = blockIdx.y * 64;
    const int n0 = blockIdx.x * 64;
    const int t  = threadIdx.x;

    #pragma unroll
    for (int j = 0; j < 16; j++) {
        const int idx = j * 256 + t;
        const int r = idx >> 6, col = idx & 63;
        s[r][col] = X[(size_t)b * CC * NN + (size_t)(c0 + r) * NN + n0 + col];
    }
    __syncthreads();
    #pragma unroll
    for (int j = 0; j < 8; j++) {
        const int idx = j * 256 + t;
        const int nl = idx >> 5, w = idx & 31;
        uint32_t hi, lo;
        split2(s[2 * w][nl], s[2 * w + 1][nl], hi, lo);
        const size_t o = ((size_t)b * NN + n0 + nl) * 128 + (c0 >> 1) + w;
        g_XPh[o] = hi;
        g_XPl[o] = lo;
    }
}

// =====================================================================
// Shared GEMM mainloop (128M x 128N CTA, K=256, chunk 32).
// =====================================================================
#define STRD 20
#define STGW (128 * STRD)

#define GEMM_MAINLOOP(AH, AL, BH, BL, M0, N0G)                                      \
    uint32_t* sAh = smw;                                                            \
    uint32_t* sAl = smw + 2 * STGW;                                                 \
    uint32_t* sBh = smw + 4 * STGW;                                                 \
    uint32_t* sBl = smw + 6 * STGW;                                                 \
    const int t = threadIdx.x;                                                      \
    const int wid = t >> 5, lane = t & 31;                                          \
    const int gr = lane >> 2, gc = lane & 3;                                        \
    const int wm = wid >> 2, wn = wid & 3;                                          \
    float acc[4][4][4];                                                             \
    _Pragma("unroll")                                                               \
    for (int a = 0; a < 4; a++)                                                     \
        _Pragma("unroll")                                                           \
        for (int bq = 0; bq < 4; bq++)                                              \
            _Pragma("unroll")                                                       \
            for (int k = 0; k < 4; k++) acc[a][bq][k] = 0.0f;                       \
    auto load_stage = [&](int ch, int st) {                                         \
        const int c0w = ch * 16;                                                    \
        _Pragma("unroll")                                                           \
        for (int j = 0; j < 2; j++) {                                               \
            const int idx = j * 256 + t;                                            \
            const int r = idx >> 2, w4 = (idx & 3) << 2;                            \
            const uint32_t soff = (st * STGW + r * STRD + w4) * 4;                  \
            CP_ASYNC16(sptr(sAh) + soff, AH + (size_t)(M0 + r) * 128 + c0w + w4);   \
            CP_ASYNC16(sptr(sAl) + soff, AL + (size_t)(M0 + r) * 128 + c0w + w4);   \
            CP_ASYNC16(sptr(sBh) + soff, BH + (size_t)(N0G + r) * 128 + c0w + w4);  \
            CP_ASYNC16(sptr(sBl) + soff, BL + (size_t)(N0G + r) * 128 + c0w + w4);  \
        }                                                                           \
    };                                                                              \
    load_stage(0, 0);                                                               \
    CP_COMMIT();                                                                    \
    CP_WAIT0();                                                                     \
    __syncthreads();                                                                \
    _Pragma("unroll 1")                                                             \
    for (int ch = 0; ch < 8; ch++) {                                                \
        const int cur = ch & 1;                                                     \
        if (ch < 7) { load_stage(ch + 1, 1 - cur); CP_COMMIT(); }                   \
        _Pragma("unroll")                                                           \
        for (int ks = 0; ks < 2; ks++) {                                            \
            uint32_t ah[4][4], al[4][4];                                            \
            _Pragma("unroll")                                                       \
            for (int mf = 0; mf < 4; mf++) {                                        \
                const int row = wm * 64 + mf * 16 + gr;                             \
                const int base = cur * STGW + row * STRD + ks * 8 + gc;             \
                ah[mf][0] = sAh[base];                                              \
                ah[mf][1] = sAh[base + 8 * STRD];                                   \
                ah[mf][2] = sAh[base + 4];                                          \
                ah[mf][3] = sAh[base + 8 * STRD + 4];                               \
                al[mf][0] = sAl[base];                                              \
                al[mf][1] = sAl[base + 8 * STRD];                                   \
                al[mf][2] = sAl[base + 4];                                          \
                al[mf][3] = sAl[base + 8 * STRD + 4];                               \
            }                                                                       \
            _Pragma("unroll")                                                       \
            for (int nf = 0; nf < 4; nf++) {                                        \
                const int rowb = wn * 32 + nf * 8 + gr;                             \
                const int bas = cur * STGW + rowb * STRD + ks * 8 + gc;             \
                const uint32_t bh0 = sBh[bas], bh1 = sBh[bas + 4];                  \
                const uint32_t bl0 = sBl[bas], bl1 = sBl[bas + 4];                  \
                _Pragma("unroll")                                                   \
                for (int mf = 0; mf < 4; mf++) {                                    \
                    mma16816(acc[mf][nf], ah[mf], bh0, bh1);                        \
                    mma16816(acc[mf][nf], al[mf], bh0, bh1);                        \
                    mma16816(acc[mf][nf], ah[mf], bl0, bl1);                        \
                }                                                                   \
            }                                                                       \
        }                                                                           \
        if (ch < 7) CP_WAIT0();                                                     \
        __syncthreads();                                                            \
    }

// =====================================================================
// QKV GEMM + layout epilogue via smem bounce.
// =====================================================================
__global__ __launch_bounds__(256) void qkv_gemm_kernel(const float* __restrict__ bias)
{
    extern __shared__ uint32_t smw[];
    const int n0g = blockIdx.x * 128;
    const int o0  = blockIdx.y * 128;

    GEMM_MAINLOOP(g_WqPh, g_WqPl, g_XPh, g_XPl, o0, n0g)

    #pragma unroll
    for (int mf = 0; mf < 4; mf++) {
        const int o_r = o0 + wm * 64 + mf * 16 + gr;
        const float b0 = bias[o_r], b1 = bias[o_r + 8];
        #pragma unroll
        for (int nf = 0; nf < 4; nf++) {
            acc[mf][nf][0] += b0; acc[mf][nf][1] += b0;
            acc[mf][nf][2] += b1; acc[mf][nf][3] += b1;
        }
    }

    float* sf = (float*)smw;
    __syncthreads();
    #pragma unroll
    for (int mf = 0; mf < 4; mf++) {
        const int o_l = wm * 64 + mf * 16 + gr;
        #pragma unroll
        for (int nf = 0; nf < 4; nf++) {
            const int n_l = wn * 32 + nf * 8 + 2 * gc;
            sf[o_l * 129 + n_l]           = acc[mf][nf][0];
            sf[o_l * 129 + n_l + 1]       = acc[mf][nf][1];
            sf[(o_l + 8) * 129 + n_l]     = acc[mf][nf][2];
            sf[(o_l + 8) * 129 + n_l + 1] = acc[mf][nf][3];
        }
    }
    __syncthreads();

    if (o0 < CC) {
        #pragma unroll 4
        for (int idx = t; idx < 8192; idx += 256) {
            const int nl = idx >> 6, w = idx & 63;
            const int ol = 2 * w;
            const float f0 = sf[ol * 129 + nl], f1 = sf[(ol + 1) * 129 + nl];
            const size_t ng = n0g + nl;
            *(float2*)(g_Q + ng * CC + o0 + ol) = make_float2(f0, f1);
        }
    } else if (o0 < 2 * CC) {
        #pragma unroll 4
        for (int idx = t; idx < 8192; idx += 256) {
            const int nl = idx >> 6, w = idx & 63;
            const int ol = 2 * w;
            uint32_t hi, lo;
            split2(sf[ol * 129 + nl], sf[(ol + 1) * 129 + nl], hi, lo);
            const int ng = n0g + nl;
            const int b = (ng >= NN) ? 1 : 0;
            const int n = ng - b * NN;
            const int d = (o0 - CC) + ol;
            const size_t off = ((size_t)(b * NH + (d >> 5)) * NN + n) * (HD/2) + ((d & 31) >> 1);
            g_KPh[off] = hi;
            g_KPl[off] = lo;
        }
    } else {
        const int b = (n0g >= NN) ? 1 : 0;
        const int nb = n0g - b * NN;
        #pragma unroll 4
        for (int idx = t; idx < 8192; idx += 256) {
            const int ol = idx >> 6, w = idx & 63;
            uint32_t hi, lo;
            split2(sf[ol * 129 + 2 * w], sf[ol * 129 + 2 * w + 1], hi, lo);
            const int d = (o0 - 2 * CC) + ol;
            const size_t off = ((size_t)(b * NH + (d >> 5)) * HD + (d & 31)) * (NN/2) + (nb >> 1) + w;
            g_VPh[off] = hi;
            g_VPl[off] = lo;
        }
    }
}

// =====================================================================
// proj GEMM + bias + residual, direct epilogue.
// =====================================================================
__global__ __launch_bounds__(256) void proj_gemm_kernel(
    const float* __restrict__ X, const float* __restrict__ bp,
    float* __restrict__ out)
{
    extern __shared__ uint32_t smw[];
    const int n0g = blockIdx.x * 128;
    const int c0  = blockIdx.y * 128;

    GEMM_MAINLOOP(g_WpPh, g_WpPl, g_OPh, g_OPl, c0, n0g)

    const int b = (n0g >= NN) ? 1 : 0;
    #pragma unroll
    for (int mf = 0; mf < 4; mf++) {
        const int c_r = c0 + wm * 64 + mf * 16 + gr;
        const float bi0 = bp[c_r], bi1 = bp[c_r + 8];
        #pragma unroll
        for (int nf = 0; nf < 4; nf++) {
            const int ngc = n0g + wn * 32 + nf * 8 + 2 * gc;
            const int n = ngc - b * NN;
            const size_t o0i = (size_t)b * CC * NN + (size_t)c_r * NN + n;
            const size_t o1i = o0i + 8 * NN;
            float2 x0 = *(const float2*)(X + o0i);
            float2 x1 = *(const float2*)(X + o1i);
            *(float2*)(out + o0i) = make_float2(acc[mf][nf][0] + bi0 + x0.x,
                                                acc[mf][nf][1] + bi0 + x0.y);
            *(float2*)(out + o1i) = make_float2(acc[mf][nf][2] + bi1 + x1.x,
                                                acc[mf][nf][3] + bi1 + x1.y);
        }
    }
}

// =====================================================================
// Flash attention: k-tile 64, 2 CTAs/SM, exp2 domain, deferred l-reduce.
// =====================================================================
#define KS 1280   // 64 rows * 20 (16 data + 4 pad)
#define VS 1152   // 32 rows * 36 (32 data + 4 pad)

__global__ __launch_bounds__(256, 2) void attn_kernel()
{
    extern __shared__ uint32_t sm[];
    uint32_t* sKh = sm;
    uint32_t* sKl = sm + 2 * KS;
    uint32_t* sVh = sm + 4 * KS;
    uint32_t* sVl = sm + 4 * KS + 2 * VS;

    const int bh = blockIdx.y;
    const int b  = bh >> 3, h = bh & 7;
    const int q0 = blockIdx.x * 128;
    const int t  = threadIdx.x;
    const int wid = t >> 5, lane = t & 31;
    const int gr = lane >> 2, gc = lane & 3;

    const uint32_t* gKh = g_KPh + (size_t)bh * NN * (HD/2);
    const uint32_t* gKl = g_KPl + (size_t)bh * NN * (HD/2);
    const uint32_t* gVh = g_VPh + (size_t)bh * HD * (NN/2);
    const uint32_t* gVl = g_VPl + (size_t)bh * HD * (NN/2);

    uint32_t aQh[2][4], aQl[2][4];
    {
        // 1/sqrt(32) * log2(e): S lands in log2 domain -> exp2 = 1 MUFU
        const float scale = 0.2550165425423146f;
        const float* Qb = g_Q + ((size_t)b * NN + q0 + wid * 16) * CC + h * HD;
        #pragma unroll
        for (int ks = 0; ks < 2; ks++) {
            #pragma unroll
            for (int p = 0; p < 4; p++) {
                const int row = gr + ((p & 1) ? 8 : 0);
                const int col = 2 * gc + ((p & 2) ? 8 : 0) + ks * 16;
                float2 q = *(const float2*)(Qb + (size_t)row * CC + col);
                q.x *= scale; q.y *= scale;
                split2(q.x, q.y, aQh[ks][p], aQl[ks][p]);
            }
        }
    }

    auto load_tile = [&](int k0, int s) {
        #pragma unroll
        for (int j = 0; j < 2; j++) {
            const int idx = j * 256 + t;
            const int arr = idx >> 8;
            const int rem = idx & 255;
            const int r = rem >> 2, chn = (rem & 3) << 2;
            const uint32_t* src = (arr ? gKl : gKh) + (size_t)(k0 + r) * (HD/2) + chn;
            CP_ASYNC16(sptr((arr ? sKl : sKh) + s * KS + r * 20 + chn), src);
        }
        #pragma unroll
        for (int j = 0; j < 2; j++) {
            const int idx = j * 256 + t;
            const int arr = idx >> 8;
            const int rem = idx & 255;
            const int r = rem >> 3, chn = (rem & 7) << 2;
            const uint32_t* src = (arr ? gVl : gVh) + (size_t)r * (NN/2) + (k0 >> 1) + chn;
            CP_ASYNC16(sptr((arr ? sVl : sVh) + s * VS + r * 36 + chn), src);
        }
    };

    float m_[2] = {-1e30f, -1e30f};
    float l_[2] = {0.0f, 0.0f};   // per-lane partials; reduced once after loop
    float o[4][4];
    #pragma unroll
    for (int nv = 0; nv < 4; nv++)
        #pragma unroll
        for (int k = 0; k < 4; k++) o[nv][k] = 0.0f;

    load_tile(0, 0);
    CP_COMMIT();
    CP_WAIT0();
    __syncthreads();

    #pragma unroll 1
    for (int kt = 0; kt < 36; kt++) {
        const int cur = kt & 1;
        if (kt < 35) { load_tile((kt + 1) * 64, 1 - cur); CP_COMMIT(); }

        // ---- S = Q K^T (3-product split), log2 domain ----
        float c[8][4];
        #pragma unroll
        for (int nf = 0; nf < 8; nf++)
            #pragma unroll
            for (int k = 0; k < 4; k++) c[nf][k] = 0.0f;

        const uint32_t* Kh = sKh + cur * KS;
        const uint32_t* Kl = sKl + cur * KS;
        #pragma unroll
        for (int nf = 0; nf < 8; nf++) {
            const int base = (nf * 8 + gr) * 20;
            #pragma unroll
            for (int ks = 0; ks < 2; ks++) {
                const uint32_t bh0 = Kh[base + ks * 8 + gc];
                const uint32_t bh1 = Kh[base + ks * 8 + 4 + gc];
                const uint32_t bl0 = Kl[base + ks * 8 + gc];
                const uint32_t bl1 = Kl[base + ks * 8 + 4 + gc];
                mma16816(c[nf], aQh[ks], bh0, bh1);
                mma16816(c[nf], aQl[ks], bh0, bh1);
                mma16816(c[nf], aQh[ks], bl0, bl1);
            }
        }

        // ---- max (only reduction on critical path) ----
        float mx0 = -1e30f, mx1 = -1e30f;
        #pragma unroll
        for (int nf = 0; nf < 8; nf++) {
            mx0 = fmaxf(mx0, fmaxf(c[nf][0], c[nf][1]));
            mx1 = fmaxf(mx1, fmaxf(c[nf][2], c[nf][3]));
        }
        mx0 = fmaxf(mx0, __shfl_xor_sync(0xffffffffu, mx0, 1));
        mx0 = fmaxf(mx0, __shfl_xor_sync(0xffffffffu, mx0, 2));
        mx1 = fmaxf(mx1, __shfl_xor_sync(0xffffffffu, mx1, 1));
        mx1 = fmaxf(mx1, __shfl_xor_sync(0xffffffffu, mx1, 2));
        const float mn0 = fmaxf(m_[0], mx0);
        const float mn1 = fmaxf(m_[1], mx1);
        const float al0 = ex2(m_[0] - mn0);
        const float al1 = ex2(m_[1] - mn1);
        m_[0] = mn0; m_[1] = mn1;

        // ---- p = exp2(s - m); per-lane partial sums (no shfl here) ----
        float s0 = 0.0f, s1 = 0.0f;
        #pragma unroll
        for (int nf = 0; nf < 8; nf++) {
            c[nf][0] = ex2(c[nf][0] - mn0);
            c[nf][1] = ex2(c[nf][1] - mn0);
            c[nf][2] = ex2(c[nf][2] - mn1);
            c[nf][3] = ex2(c[nf][3] - mn1);
            s0 += c[nf][0] + c[nf][1];
            s1 += c[nf][2] + c[nf][3];
        }
        l_[0] = l_[0] * al0 + s0;
        l_[1] = l_[1] * al1 + s1;

        #pragma unroll
        for (int nv = 0; nv < 4; nv++) {
            o[nv][0] *= al0; o[nv][1] *= al0;
            o[nv][2] *= al1; o[nv][3] *= al1;
        }

        // ---- O += P V (3-product split) ----
        const uint32_t* Vh = sVh + cur * VS;
        const uint32_t* Vl = sVl + cur * VS;
        #pragma unroll
        for (int j = 0; j < 4; j++) {
            uint32_t pAh[4], pAl[4];
            split2(c[2*j][0],   c[2*j][1],   pAh[0], pAl[0]);
            split2(c[2*j][2],   c[2*j][3],   pAh[1], pAl[1]);
            split2(c[2*j+1][0], c[2*j+1][1], pAh[2], pAl[2]);
            split2(c[2*j+1][2], c[2*j+1][3], pAh[3], pAl[3]);
            #pragma unroll
            for (int nv = 0; nv < 4; nv++) {
                const int vb = (nv * 8 + gr) * 36 + j * 8;
                const uint32_t vh0 = Vh[vb + gc], vh1 = Vh[vb + 4 + gc];
                const uint32_t vl0 = Vl[vb + gc], vl1 = Vl[vb + 4 + gc];
                mma16816(o[nv], pAh, vh0, vh1);
                mma16816(o[nv], pAl, vh0, vh1);
                mma16816(o[nv], pAh, vl0, vl1);
            }
        }

        CP_WAIT0();
        __syncthreads();
    }

    // ---- deferred l reduction (once) + finalize ----
    l_[0] += __shfl_xor_sync(0xffffffffu, l_[0], 1);
    l_[0] += __shfl_xor_sync(0xffffffffu, l_[0], 2);
    l_[1] += __shfl_xor_sync(0xffffffffu, l_[1], 1);
    l_[1] += __shfl_xor_sync(0xffffffffu, l_[1], 2);
    const float inv0 = 1.0f / l_[0];
    const float inv1 = 1.0f / l_[1];
    const size_t ng0 = (size_t)b * NN + q0 + wid * 16 + gr;
    const size_t ng1 = ng0 + 8;
    #pragma unroll
    for (int nv = 0; nv < 4; nv++) {
        const int wrd = h * 16 + nv * 4 + gc;
        uint32_t hi, lo;
        split2(o[nv][0] * inv0, o[nv][1] * inv0, hi, lo);
        g_OPh[ng0 * 128 + wrd] = hi;
        g_OPl[ng0 * 128 + wrd] = lo;
        split2(o[nv][2] * inv1, o[nv][3] * inv1, hi, lo);
        g_OPh[ng1 * 128 + wrd] = hi;
        g_OPl[ng1 * 128 + wrd] = lo;
    }
}

// =====================================================================
extern "C" void kernel_launch(void* const* d_in, const int* in_sizes, int n_in,
                              void* d_out, int out_size)
{
    const float* x      = (const float*)d_in[0];
    const float* w_qkv  = (const float*)d_in[1];
    const float* b_qkv  = (const float*)d_in[2];
    const float* w_proj = (const float*)d_in[3];
    const float* b_proj = (const float*)d_in[4];
    float* out = (float*)d_out;

    static bool attr_done = false;
    const int gemm_smem = 8 * STGW * 4;              // 81920 B
    const int attn_smem = (4 * KS + 4 * VS) * 4;     // 38912 B
    if (!attr_done) {
        cudaFuncSetAttribute(qkv_gemm_kernel, cudaFuncAttributeMaxDynamicSharedMemorySize, gemm_smem);
        cudaFuncSetAttribute(proj_gemm_kernel, cudaFuncAttributeMaxDynamicSharedMemorySize, gemm_smem);
        cudaFuncSetAttribute(attn_kernel, cudaFuncAttributeMaxDynamicSharedMemorySize, attn_smem);
        attr_done = true;
    }

    split_w_kernel<<<(OC3 + CC) * 128 / 256, 256>>>(w_qkv, w_proj);
    split_x_kernel<<<dim3(NN / 64, CC / 64, BB), 256>>>(x);
    qkv_gemm_kernel<<<dim3(NG / 128, OC3 / 128), 256, gemm_smem>>>(b_qkv);
    attn_kernel<<<dim3(NN / 128, NBH), 256, attn_smem>>>();
    proj_gemm_kernel<<<dim3(NG / 128, CC / 128), 256, gemm_smem>>>(x, b_proj, out);
}

// round 7
// speedup vs baseline: 3.4526x; 1.1561x over previous
#include <cuda_runtime.h>
#include <cuda_bf16.h>
#include <cstdint>

#define BB   2
#define CC   256
#define NN   2304
#define OC3  768
#define NH   8
#define HD   32
#define NBH  (BB*NH)
#define NG   (BB*NN)     // 4608 flattened (b,n)

// ---------------- device scratch ----------------
__device__ float g_Q[NG * CC];                               // Q fp32 [ng][c]
__device__ __align__(16) uint32_t g_XPh[NG * 128];           // X split pairs along c [ng][c/2]
__device__ __align__(16) uint32_t g_XPl[NG * 128];
__device__ __align__(16) uint32_t g_WqPh[OC3 * 128];         // W_qkv split [o][c/2]
__device__ __align__(16) uint32_t g_WqPl[OC3 * 128];
__device__ __align__(16) uint32_t g_WpPh[CC * 128];          // W_proj split [c][c'/2]
__device__ __align__(16) uint32_t g_WpPl[CC * 128];
__device__ __align__(16) uint32_t g_KPh[NBH * NN * (HD/2)];  // K pairs along d [bh][n][d/2]
__device__ __align__(16) uint32_t g_KPl[NBH * NN * (HD/2)];
__device__ __align__(16) uint32_t g_VPh[NBH * HD * (NN/2)];  // V^T bf16 pairs along n [bh][d][n/2]
__device__ __align__(16) uint32_t g_OPh[NG * 128];           // attn out split [ng][c/2]
__device__ __align__(16) uint32_t g_OPl[NG * 128];

// ---------------- helpers ----------------
__device__ __forceinline__ uint32_t bf2_pack(float lo_elem, float hi_elem) {
    uint32_t d;
    asm("cvt.rn.bf16x2.f32 %0, %1, %2;" : "=r"(d) : "f"(hi_elem), "f"(lo_elem));
    return d;
}
__device__ __forceinline__ float2 bf2_unpack(uint32_t v) {
    __nv_bfloat162 h;
    *reinterpret_cast<uint32_t*>(&h) = v;
    return __bfloat1622float2(h);
}
__device__ __forceinline__ void split2(float x, float y, uint32_t& hi, uint32_t& lo) {
    hi = bf2_pack(x, y);
    float2 f = bf2_unpack(hi);
    lo = bf2_pack(x - f.x, y - f.y);
}
__device__ __forceinline__ void mma16816(float c[4], const uint32_t a[4], uint32_t b0, uint32_t b1) {
    asm volatile(
        "mma.sync.aligned.m16n8k16.row.col.f32.bf16.bf16.f32 "
        "{%0,%1,%2,%3}, {%4,%5,%6,%7}, {%8,%9}, {%0,%1,%2,%3};"
        : "+f"(c[0]), "+f"(c[1]), "+f"(c[2]), "+f"(c[3])
        : "r"(a[0]), "r"(a[1]), "r"(a[2]), "r"(a[3]), "r"(b0), "r"(b1));
}
__device__ __forceinline__ float ex2(float x) {
    float r;
    asm("ex2.approx.f32 %0, %1;" : "=f"(r) : "f"(x));
    return r;
}
#define CP_ASYNC16(dst, src) \
    asm volatile("cp.async.cg.shared.global [%0], [%1], 16;" :: "r"(dst), "l"(src))
#define CP_COMMIT() asm volatile("cp.async.commit_group;")
#define CP_WAIT0()  asm volatile("cp.async.wait_group 0;" ::: "memory")
__device__ __forceinline__ uint32_t sptr(const void* p) {
    return (uint32_t)__cvta_generic_to_shared(p);
}

// =====================================================================
// Prep A: split weights into bf16x2 hi/lo words (pairs along input chan).
// =====================================================================
__global__ __launch_bounds__(256) void split_w_kernel(
    const float* __restrict__ Wq, const float* __restrict__ Wp)
{
    const int idx = blockIdx.x * 256 + threadIdx.x;  // 131072 total
    const int r = idx >> 7, w = idx & 127;
    if (r < OC3) {
        float2 f = *(const float2*)(Wq + (size_t)r * CC + 2 * w);
        uint32_t hi, lo;
        split2(f.x, f.y, hi, lo);
        g_WqPh[r * 128 + w] = hi;
        g_WqPl[r * 128 + w] = lo;
    } else {
        const int rr = r - OC3;
        float2 f = *(const float2*)(Wp + (size_t)rr * CC + 2 * w);
        uint32_t hi, lo;
        split2(f.x, f.y, hi, lo);
        g_WpPh[rr * 128 + w] = hi;
        g_WpPl[rr * 128 + w] = lo;
    }
}

// =====================================================================
// Prep B: transpose-split X [b][c][n] -> pairs along c, [ng][c/2].
// =====================================================================
__global__ __launch_bounds__(256) void split_x_kernel(const float* __restrict__ X)
{
    __shared__ float s[64][65];
    const int b  = blockIdx.z;
    const int c0 = blockIdx.y * 64;
    const int n0 = blockIdx.x * 64;
    const int t  = threadIdx.x;

    #pragma unroll
    for (int j = 0; j < 16; j++) {
        const int idx = j * 256 + t;
        const int r = idx >> 6, col = idx & 63;
        s[r][col] = X[(size_t)b * CC * NN + (size_t)(c0 + r) * NN + n0 + col];
    }
    __syncthreads();
    #pragma unroll
    for (int j = 0; j < 8; j++) {
        const int idx = j * 256 + t;
        const int nl = idx >> 5, w = idx & 31;
        uint32_t hi, lo;
        split2(s[2 * w][nl], s[2 * w + 1][nl], hi, lo);
        const size_t o = ((size_t)b * NN + n0 + nl) * 128 + (c0 >> 1) + w;
        g_XPh[o] = hi;
        g_XPl[o] = lo;
    }
}

// =====================================================================
// Shared GEMM mainloop (128M x 128N CTA, K=256, chunk 32).
// =====================================================================
#define STRD 20
#define STGW (128 * STRD)

#define GEMM_MAINLOOP(AH, AL, BH, BL, M0, N0G)                                      \
    uint32_t* sAh = smw;                                                            \
    uint32_t* sAl = smw + 2 * STGW;                                                 \
    uint32_t* sBh = smw + 4 * STGW;                                                 \
    uint32_t* sBl = smw + 6 * STGW;                                                 \
    const int t = threadIdx.x;                                                      \
    const int wid = t >> 5, lane = t & 31;                                          \
    const int gr = lane >> 2, gc = lane & 3;                                        \
    const int wm = wid >> 2, wn = wid & 3;                                          \
    float acc[4][4][4];                                                             \
    _Pragma("unroll")                                                               \
    for (int a = 0; a < 4; a++)                                                     \
        _Pragma("unroll")                                                           \
        for (int bq = 0; bq < 4; bq++)                                              \
            _Pragma("unroll")                                                       \
            for (int k = 0; k < 4; k++) acc[a][bq][k] = 0.0f;                       \
    auto load_stage = [&](int ch, int st) {                                         \
        const int c0w = ch * 16;                                                    \
        _Pragma("unroll")                                                           \
        for (int j = 0; j < 2; j++) {                                               \
            const int idx = j * 256 + t;                                            \
            const int r = idx >> 2, w4 = (idx & 3) << 2;                            \
            const uint32_t soff = (st * STGW + r * STRD + w4) * 4;                  \
            CP_ASYNC16(sptr(sAh) + soff, AH + (size_t)(M0 + r) * 128 + c0w + w4);   \
            CP_ASYNC16(sptr(sAl) + soff, AL + (size_t)(M0 + r) * 128 + c0w + w4);   \
            CP_ASYNC16(sptr(sBh) + soff, BH + (size_t)(N0G + r) * 128 + c0w + w4);  \
            CP_ASYNC16(sptr(sBl) + soff, BL + (size_t)(N0G + r) * 128 + c0w + w4);  \
        }                                                                           \
    };                                                                              \
    load_stage(0, 0);                                                               \
    CP_COMMIT();                                                                    \
    CP_WAIT0();                                                                     \
    __syncthreads();                                                                \
    _Pragma("unroll 1")                                                             \
    for (int ch = 0; ch < 8; ch++) {                                                \
        const int cur = ch & 1;                                                     \
        if (ch < 7) { load_stage(ch + 1, 1 - cur); CP_COMMIT(); }                   \
        _Pragma("unroll")                                                           \
        for (int ks = 0; ks < 2; ks++) {                                            \
            uint32_t ah[4][4], al[4][4];                                            \
            _Pragma("unroll")                                                       \
            for (int mf = 0; mf < 4; mf++) {                                        \
                const int row = wm * 64 + mf * 16 + gr;                             \
                const int base = cur * STGW + row * STRD + ks * 8 + gc;             \
                ah[mf][0] = sAh[base];                                              \
                ah[mf][1] = sAh[base + 8 * STRD];                                   \
                ah[mf][2] = sAh[base + 4];                                          \
                ah[mf][3] = sAh[base + 8 * STRD + 4];                               \
                al[mf][0] = sAl[base];                                              \
                al[mf][1] = sAl[base + 8 * STRD];                                   \
                al[mf][2] = sAl[base + 4];                                          \
                al[mf][3] = sAl[base + 8 * STRD + 4];                               \
            }                                                                       \
            _Pragma("unroll")                                                       \
            for (int nf = 0; nf < 4; nf++) {                                        \
                const int rowb = wn * 32 + nf * 8 + gr;                             \
                const int bas = cur * STGW + rowb * STRD + ks * 8 + gc;             \
                const uint32_t bh0 = sBh[bas], bh1 = sBh[bas + 4];                  \
                const uint32_t bl0 = sBl[bas], bl1 = sBl[bas + 4];                  \
                _Pragma("unroll")                                                   \
                for (int mf = 0; mf < 4; mf++) {                                    \
                    mma16816(acc[mf][nf], ah[mf], bh0, bh1);                        \
                    mma16816(acc[mf][nf], al[mf], bh0, bh1);                        \
                    mma16816(acc[mf][nf], ah[mf], bl0, bl1);                        \
                }                                                                   \
            }                                                                       \
        }                                                                           \
        if (ch < 7) CP_WAIT0();                                                     \
        __syncthreads();                                                            \
    }

// =====================================================================
// QKV GEMM + layout epilogue via smem bounce.
// =====================================================================
__global__ __launch_bounds__(256) void qkv_gemm_kernel(const float* __restrict__ bias)
{
    extern __shared__ uint32_t smw[];
    const int n0g = blockIdx.x * 128;
    const int o0  = blockIdx.y * 128;

    GEMM_MAINLOOP(g_WqPh, g_WqPl, g_XPh, g_XPl, o0, n0g)

    #pragma unroll
    for (int mf = 0; mf < 4; mf++) {
        const int o_r = o0 + wm * 64 + mf * 16 + gr;
        const float b0 = bias[o_r], b1 = bias[o_r + 8];
        #pragma unroll
        for (int nf = 0; nf < 4; nf++) {
            acc[mf][nf][0] += b0; acc[mf][nf][1] += b0;
            acc[mf][nf][2] += b1; acc[mf][nf][3] += b1;
        }
    }

    float* sf = (float*)smw;
    __syncthreads();
    #pragma unroll
    for (int mf = 0; mf < 4; mf++) {
        const int o_l = wm * 64 + mf * 16 + gr;
        #pragma unroll
        for (int nf = 0; nf < 4; nf++) {
            const int n_l = wn * 32 + nf * 8 + 2 * gc;
            sf[o_l * 129 + n_l]           = acc[mf][nf][0];
            sf[o_l * 129 + n_l + 1]       = acc[mf][nf][1];
            sf[(o_l + 8) * 129 + n_l]     = acc[mf][nf][2];
            sf[(o_l + 8) * 129 + n_l + 1] = acc[mf][nf][3];
        }
    }
    __syncthreads();

    if (o0 < CC) {
        #pragma unroll 4
        for (int idx = t; idx < 8192; idx += 256) {
            const int nl = idx >> 6, w = idx & 63;
            const int ol = 2 * w;
            const float f0 = sf[ol * 129 + nl], f1 = sf[(ol + 1) * 129 + nl];
            const size_t ng = n0g + nl;
            *(float2*)(g_Q + ng * CC + o0 + ol) = make_float2(f0, f1);
        }
    } else if (o0 < 2 * CC) {
        #pragma unroll 4
        for (int idx = t; idx < 8192; idx += 256) {
            const int nl = idx >> 6, w = idx & 63;
            const int ol = 2 * w;
            uint32_t hi, lo;
            split2(sf[ol * 129 + nl], sf[(ol + 1) * 129 + nl], hi, lo);
            const int ng = n0g + nl;
            const int b = (ng >= NN) ? 1 : 0;
            const int n = ng - b * NN;
            const int d = (o0 - CC) + ol;
            const size_t off = ((size_t)(b * NH + (d >> 5)) * NN + n) * (HD/2) + ((d & 31) >> 1);
            g_KPh[off] = hi;
            g_KPl[off] = lo;
        }
    } else {
        // V region: single bf16 (hi only), pairs along n -> [bh][d][n/2]
        const int b = (n0g >= NN) ? 1 : 0;
        const int nb = n0g - b * NN;
        #pragma unroll 4
        for (int idx = t; idx < 8192; idx += 256) {
            const int ol = idx >> 6, w = idx & 63;
            const uint32_t hi = bf2_pack(sf[ol * 129 + 2 * w], sf[ol * 129 + 2 * w + 1]);
            const int d = (o0 - 2 * CC) + ol;
            const size_t off = ((size_t)(b * NH + (d >> 5)) * HD + (d & 31)) * (NN/2) + (nb >> 1) + w;
            g_VPh[off] = hi;
        }
    }
}

// =====================================================================
// proj GEMM + bias + residual, direct epilogue.
// =====================================================================
__global__ __launch_bounds__(256) void proj_gemm_kernel(
    const float* __restrict__ X, const float* __restrict__ bp,
    float* __restrict__ out)
{
    extern __shared__ uint32_t smw[];
    const int n0g = blockIdx.x * 128;
    const int c0  = blockIdx.y * 128;

    GEMM_MAINLOOP(g_WpPh, g_WpPl, g_OPh, g_OPl, c0, n0g)

    const int b = (n0g >= NN) ? 1 : 0;
    #pragma unroll
    for (int mf = 0; mf < 4; mf++) {
        const int c_r = c0 + wm * 64 + mf * 16 + gr;
        const float bi0 = bp[c_r], bi1 = bp[c_r + 8];
        #pragma unroll
        for (int nf = 0; nf < 4; nf++) {
            const int ngc = n0g + wn * 32 + nf * 8 + 2 * gc;
            const int n = ngc - b * NN;
            const size_t o0i = (size_t)b * CC * NN + (size_t)c_r * NN + n;
            const size_t o1i = o0i + 8 * NN;
            float2 x0 = *(const float2*)(X + o0i);
            float2 x1 = *(const float2*)(X + o1i);
            *(float2*)(out + o0i) = make_float2(acc[mf][nf][0] + bi0 + x0.x,
                                                acc[mf][nf][1] + bi0 + x0.y);
            *(float2*)(out + o1i) = make_float2(acc[mf][nf][2] + bi1 + x1.x,
                                                acc[mf][nf][3] + bi1 + x1.y);
        }
    }
}

// =====================================================================
// Flash attention: k-tile 64, 2 CTAs/SM, exp2 domain.
// S: 3-product split. PV: single bf16 product; l computed from rounded P
// so dominant-term rounding cancels in O/l.
// smem/CTA: (4*KS + 2*VS)*4 = 29696 B.
// =====================================================================
#define KS 1280   // 64 rows * 20 (16 data + 4 pad)
#define VS 1152   // 32 rows * 36 (32 data + 4 pad)

__global__ __launch_bounds__(256, 2) void attn_kernel()
{
    extern __shared__ uint32_t sm[];
    uint32_t* sKh = sm;
    uint32_t* sKl = sm + 2 * KS;
    uint32_t* sVh = sm + 4 * KS;

    const int bh = blockIdx.y;
    const int b  = bh >> 3, h = bh & 7;
    const int q0 = blockIdx.x * 128;
    const int t  = threadIdx.x;
    const int wid = t >> 5, lane = t & 31;
    const int gr = lane >> 2, gc = lane & 3;

    const uint32_t* gKh = g_KPh + (size_t)bh * NN * (HD/2);
    const uint32_t* gKl = g_KPl + (size_t)bh * NN * (HD/2);
    const uint32_t* gVh = g_VPh + (size_t)bh * HD * (NN/2);

    uint32_t aQh[2][4], aQl[2][4];
    {
        // 1/sqrt(32) * log2(e): S lands in log2 domain -> exp2 = 1 MUFU
        const float scale = 0.2550165425423146f;
        const float* Qb = g_Q + ((size_t)b * NN + q0 + wid * 16) * CC + h * HD;
        #pragma unroll
        for (int ks = 0; ks < 2; ks++) {
            #pragma unroll
            for (int p = 0; p < 4; p++) {
                const int row = gr + ((p & 1) ? 8 : 0);
                const int col = 2 * gc + ((p & 2) ? 8 : 0) + ks * 16;
                float2 q = *(const float2*)(Qb + (size_t)row * CC + col);
                q.x *= scale; q.y *= scale;
                split2(q.x, q.y, aQh[ks][p], aQl[ks][p]);
            }
        }
    }

    auto load_tile = [&](int k0, int s) {
        #pragma unroll
        for (int j = 0; j < 2; j++) {                       // K hi+lo: 512 chunks
            const int idx = j * 256 + t;
            const int arr = idx >> 8;
            const int rem = idx & 255;
            const int r = rem >> 2, chn = (rem & 3) << 2;
            const uint32_t* src = (arr ? gKl : gKh) + (size_t)(k0 + r) * (HD/2) + chn;
            CP_ASYNC16(sptr((arr ? sKl : sKh) + s * KS + r * 20 + chn), src);
        }
        {                                                   // V hi: 256 chunks
            const int r = t >> 3, chn = (t & 7) << 2;
            const uint32_t* src = gVh + (size_t)r * (NN/2) + (k0 >> 1) + chn;
            CP_ASYNC16(sptr(sVh + s * VS + r * 36 + chn), src);
        }
    };

    float m_[2] = {-1e30f, -1e30f};
    float l_[2] = {0.0f, 0.0f};   // per-lane partials from ROUNDED p
    float o[4][4];
    #pragma unroll
    for (int nv = 0; nv < 4; nv++)
        #pragma unroll
        for (int k = 0; k < 4; k++) o[nv][k] = 0.0f;

    load_tile(0, 0);
    CP_COMMIT();
    CP_WAIT0();
    __syncthreads();

    #pragma unroll 1
    for (int kt = 0; kt < 36; kt++) {
        const int cur = kt & 1;
        if (kt < 35) { load_tile((kt + 1) * 64, 1 - cur); CP_COMMIT(); }

        // ---- S = Q K^T (3-product split), log2 domain ----
        float c[8][4];
        #pragma unroll
        for (int nf = 0; nf < 8; nf++)
            #pragma unroll
            for (int k = 0; k < 4; k++) c[nf][k] = 0.0f;

        const uint32_t* Kh = sKh + cur * KS;
        const uint32_t* Kl = sKl + cur * KS;
        #pragma unroll
        for (int nf = 0; nf < 8; nf++) {
            const int base = (nf * 8 + gr) * 20;
            #pragma unroll
            for (int ks = 0; ks < 2; ks++) {
                const uint32_t bh0 = Kh[base + ks * 8 + gc];
                const uint32_t bh1 = Kh[base + ks * 8 + 4 + gc];
                const uint32_t bl0 = Kl[base + ks * 8 + gc];
                const uint32_t bl1 = Kl[base + ks * 8 + 4 + gc];
                mma16816(c[nf], aQh[ks], bh0, bh1);
                mma16816(c[nf], aQl[ks], bh0, bh1);
                mma16816(c[nf], aQh[ks], bl0, bl1);
            }
        }

        // ---- max reduce ----
        float mx0 = -1e30f, mx1 = -1e30f;
        #pragma unroll
        for (int nf = 0; nf < 8; nf++) {
            mx0 = fmaxf(mx0, fmaxf(c[nf][0], c[nf][1]));
            mx1 = fmaxf(mx1, fmaxf(c[nf][2], c[nf][3]));
        }
        mx0 = fmaxf(mx0, __shfl_xor_sync(0xffffffffu, mx0, 1));
        mx0 = fmaxf(mx0, __shfl_xor_sync(0xffffffffu, mx0, 2));
        mx1 = fmaxf(mx1, __shfl_xor_sync(0xffffffffu, mx1, 1));
        mx1 = fmaxf(mx1, __shfl_xor_sync(0xffffffffu, mx1, 2));
        const float mn0 = fmaxf(m_[0], mx0);
        const float mn1 = fmaxf(m_[1], mx1);
        const float al0 = ex2(m_[0] - mn0);
        const float al1 = ex2(m_[1] - mn1);
        m_[0] = mn0; m_[1] = mn1;

        // ---- p = exp2(s - m) ----
        #pragma unroll
        for (int nf = 0; nf < 8; nf++) {
            c[nf][0] = ex2(c[nf][0] - mn0);
            c[nf][1] = ex2(c[nf][1] - mn0);
            c[nf][2] = ex2(c[nf][2] - mn1);
            c[nf][3] = ex2(c[nf][3] - mn1);
        }

        #pragma unroll
        for (int nv = 0; nv < 4; nv++) {
            o[nv][0] *= al0; o[nv][1] *= al0;
            o[nv][2] *= al1; o[nv][3] *= al1;
        }

        // ---- O += P V (single bf16 product; l from rounded P) ----
        const uint32_t* Vh = sVh + cur * VS;
        float s0 = 0.0f, s1 = 0.0f;
        #pragma unroll
        for (int j = 0; j < 4; j++) {
            uint32_t pA[4];
            pA[0] = bf2_pack(c[2*j][0],   c[2*j][1]);
            pA[1] = bf2_pack(c[2*j][2],   c[2*j][3]);
            pA[2] = bf2_pack(c[2*j+1][0], c[2*j+1][1]);
            pA[3] = bf2_pack(c[2*j+1][2], c[2*j+1][3]);
            const float2 f0 = bf2_unpack(pA[0]);
            const float2 f1 = bf2_unpack(pA[1]);
            const float2 f2 = bf2_unpack(pA[2]);
            const float2 f3 = bf2_unpack(pA[3]);
            s0 += (f0.x + f0.y) + (f2.x + f2.y);
            s1 += (f1.x + f1.y) + (f3.x + f3.y);
            #pragma unroll
            for (int nv = 0; nv < 4; nv++) {
                const int vb = (nv * 8 + gr) * 36 + j * 8;
                mma16816(o[nv], pA, Vh[vb + gc], Vh[vb + 4 + gc]);
            }
        }
        l_[0] = l_[0] * al0 + s0;
        l_[1] = l_[1] * al1 + s1;

        CP_WAIT0();
        __syncthreads();
    }

    // ---- deferred l reduction + finalize ----
    l_[0] += __shfl_xor_sync(0xffffffffu, l_[0], 1);
    l_[0] += __shfl_xor_sync(0xffffffffu, l_[0], 2);
    l_[1] += __shfl_xor_sync(0xffffffffu, l_[1], 1);
    l_[1] += __shfl_xor_sync(0xffffffffu, l_[1], 2);
    const float inv0 = 1.0f / l_[0];
    const float inv1 = 1.0f / l_[1];
    const size_t ng0 = (size_t)b * NN + q0 + wid * 16 + gr;
    const size_t ng1 = ng0 + 8;
    #pragma unroll
    for (int nv = 0; nv < 4; nv++) {
        const int wrd = h * 16 + nv * 4 + gc;
        uint32_t hi, lo;
        split2(o[nv][0] * inv0, o[nv][1] * inv0, hi, lo);
        g_OPh[ng0 * 128 + wrd] = hi;
        g_OPl[ng0 * 128 + wrd] = lo;
        split2(o[nv][2] * inv1, o[nv][3] * inv1, hi, lo);
        g_OPh[ng1 * 128 + wrd] = hi;
        g_OPl[ng1 * 128 + wrd] = lo;
    }
}

// =====================================================================
extern "C" void kernel_launch(void* const* d_in, const int* in_sizes, int n_in,
                              void* d_out, int out_size)
{
    const float* x      = (const float*)d_in[0];
    const float* w_qkv  = (const float*)d_in[1];
    const float* b_qkv  = (const float*)d_in[2];
    const float* w_proj = (const float*)d_in[3];
    const float* b_proj = (const float*)d_in[4];
    float* out = (float*)d_out;

    static bool attr_done = false;
    const int gemm_smem = 8 * STGW * 4;              // 81920 B
    const int attn_smem = (4 * KS + 2 * VS) * 4;     // 29696 B
    if (!attr_done) {
        cudaFuncSetAttribute(qkv_gemm_kernel, cudaFuncAttributeMaxDynamicSharedMemorySize, gemm_smem);
        cudaFuncSetAttribute(proj_gemm_kernel, cudaFuncAttributeMaxDynamicSharedMemorySize, gemm_smem);
        cudaFuncSetAttribute(attn_kernel, cudaFuncAttributeMaxDynamicSharedMemorySize, attn_smem);
        attr_done = true;
    }

    split_w_kernel<<<(OC3 + CC) * 128 / 256, 256>>>(w_qkv, w_proj);
    split_x_kernel<<<dim3(NN / 64, CC / 64, BB), 256>>>(x);
    qkv_gemm_kernel<<<dim3(NG / 128, OC3 / 128), 256, gemm_smem>>>(b_qkv);
    attn_kernel<<<dim3(NN / 128, NBH), 256, attn_smem>>>();
    proj_gemm_kernel<<<dim3(NG / 128, CC / 128), 256, gemm_smem>>>(x, b_proj, out);
}